// round 1
// baseline (speedup 1.0000x reference)
#include <cuda_runtime.h>

// Problem dims (fixed by the dataset)
#define T_TOKENS 8192      // B*S = 4*2048
#define DIM      1024      // D
#define FF       2048      // F
#define NEXP     8         // E
#define RH       128       // router hidden
#define NSLOTS   (T_TOKENS * 2)   // top-2 slots

// -------- scratch (static device globals; no allocations allowed) --------
__device__ float g_hidden[T_TOKENS * RH];                 // 4.2 MB
__device__ float g_h[(long long)NSLOTS * FF];             // 134 MB
__device__ float g_y[(long long)NSLOTS * DIM];            // 67 MB
__device__ int   g_tok[NEXP * T_TOKENS];
__device__ int   g_slot[NEXP * T_TOKENS];
__device__ float g_rw[NSLOTS];
__device__ int   g_cnt[NEXP];

// -------- tiled fp32 GEMM with optional gather/scatter + SiLU ------------
#define BM 128
#define BN 128
#define BK 16
#define TM 8
#define TN 8
#define PAD 4

__device__ __forceinline__ float silu_f(float v) {
    return v / (1.0f + __expf(-v));
}

template <bool SILU>
__global__ __launch_bounds__(256, 2)
void gemm_kernel(const float* __restrict__ A, int lda,
                 const float* __restrict__ B, long long strideB, int ldb,
                 float* __restrict__ C, int ldc,
                 const int* __restrict__ gatherA,
                 const int* __restrict__ scatterC,
                 const int* __restrict__ counts, int Mfixed, int K)
{
    const int e  = blockIdx.z;
    const int M  = counts ? counts[e] : Mfixed;
    const int m0 = blockIdx.y * BM;
    if (m0 >= M) return;
    const int n0 = blockIdx.x * BN;

    const float* Bp = B + (long long)e * strideB;
    const int* gl = gatherA  ? gatherA  + e * T_TOKENS : (const int*)0;
    const int* sl = scatterC ? scatterC + e * T_TOKENS : (const int*)0;

    __shared__ float As[2][BK][BM + PAD];
    __shared__ float Bs[2][BK][BN];

    const int tid = threadIdx.x;
    const int tm  = (tid >> 4) * TM;   // 16 thread-rows
    const int tn  = (tid & 15) * TN;   // 16 thread-cols

    // A loader: 2 float4 per thread covering 128x16 tile
    const float* aPtr[2]; int aR[2], aC[2]; bool aV[2];
#pragma unroll
    for (int i = 0; i < 2; i++) {
        int lin = tid + i * 256;        // 0..511
        aR[i] = lin >> 2;               // 0..127 (tile row)
        aC[i] = (lin & 3) * 4;          // 0,4,8,12 (k col)
        int m = m0 + aR[i];
        aV[i] = (m < M);
        int grow = 0;
        if (aV[i]) grow = gl ? gl[m] : m;
        aPtr[i] = A + (long long)grow * lda + aC[i];
    }
    // B loader: 2 float4 per thread covering 16x128 tile
    const float* bPtr[2]; int bR[2], bC[2];
#pragma unroll
    for (int i = 0; i < 2; i++) {
        int lin = tid + i * 256;
        bR[i] = lin >> 5;               // 0..15 (k row)
        bC[i] = (lin & 31) * 4;         // 0..124 (n col)
        bPtr[i] = Bp + (long long)bR[i] * ldb + n0 + bC[i];
    }

    float acc[TM][TN];
#pragma unroll
    for (int i = 0; i < TM; i++)
#pragma unroll
        for (int j = 0; j < TN; j++) acc[i][j] = 0.0f;

    float4 av[2], bv[2];
    // prologue: load k-tile 0 into buffer 0
#pragma unroll
    for (int i = 0; i < 2; i++) {
        av[i] = aV[i] ? *(const float4*)(aPtr[i]) : make_float4(0.f, 0.f, 0.f, 0.f);
        bv[i] = *(const float4*)(bPtr[i]);
    }
#pragma unroll
    for (int i = 0; i < 2; i++) {
        As[0][aC[i] + 0][aR[i]] = av[i].x;
        As[0][aC[i] + 1][aR[i]] = av[i].y;
        As[0][aC[i] + 2][aR[i]] = av[i].z;
        As[0][aC[i] + 3][aR[i]] = av[i].w;
        *(float4*)&Bs[0][bR[i]][bC[i]] = bv[i];
    }
    __syncthreads();

    const int nk = K / BK;
    for (int kt = 0; kt < nk; kt++) {
        const int buf = kt & 1;
        const bool pref = (kt + 1 < nk);
        if (pref) {
            const int k0 = (kt + 1) * BK;
#pragma unroll
            for (int i = 0; i < 2; i++) {
                av[i] = aV[i] ? *(const float4*)(aPtr[i] + k0)
                              : make_float4(0.f, 0.f, 0.f, 0.f);
                bv[i] = *(const float4*)(bPtr[i] + (long long)k0 * ldb);
            }
        }
#pragma unroll
        for (int kk = 0; kk < BK; kk++) {
            float a[TM], b[TN];
#pragma unroll
            for (int i = 0; i < TM; i++) a[i] = As[buf][kk][tm + i];
#pragma unroll
            for (int j = 0; j < TN; j++) b[j] = Bs[buf][kk][tn + j];
#pragma unroll
            for (int i = 0; i < TM; i++)
#pragma unroll
                for (int j = 0; j < TN; j++) acc[i][j] += a[i] * b[j];
        }
        if (pref) {
            const int nb = buf ^ 1;
#pragma unroll
            for (int i = 0; i < 2; i++) {
                As[nb][aC[i] + 0][aR[i]] = av[i].x;
                As[nb][aC[i] + 1][aR[i]] = av[i].y;
                As[nb][aC[i] + 2][aR[i]] = av[i].z;
                As[nb][aC[i] + 3][aR[i]] = av[i].w;
                *(float4*)&Bs[nb][bR[i]][bC[i]] = bv[i];
            }
        }
        __syncthreads();
    }

    // epilogue: scatter rows
#pragma unroll
    for (int i = 0; i < TM; i++) {
        int m = m0 + tm + i;
        if (m < M) {
            long long crow = sl ? (long long)sl[m] : (long long)m;
            float* cp = C + crow * (long long)ldc + n0 + tn;
#pragma unroll
            for (int j = 0; j < TN; j += 4) {
                float4 v;
                v.x = acc[i][j + 0]; v.y = acc[i][j + 1];
                v.z = acc[i][j + 2]; v.w = acc[i][j + 3];
                if (SILU) {
                    v.x = silu_f(v.x); v.y = silu_f(v.y);
                    v.z = silu_f(v.z); v.w = silu_f(v.w);
                }
                *(float4*)(cp + j) = v;
            }
        }
    }
}

// -------- router: logits -> softmax -> top-2 -> renorm + build lists ------
__global__ void router_topk_kernel(const float* __restrict__ hidden,
                                   const float* __restrict__ w2)
{
    const int warp = (blockIdx.x * blockDim.x + threadIdx.x) >> 5;
    const int lane = threadIdx.x & 31;
    if (warp >= T_TOKENS) return;
    const float* h = hidden + warp * RH;

    float acc[NEXP];
#pragma unroll
    for (int e = 0; e < NEXP; e++) acc[e] = 0.0f;
    for (int j = lane; j < RH; j += 32) {
        float hv = h[j];
#pragma unroll
        for (int e = 0; e < NEXP; e++) acc[e] += hv * w2[j * NEXP + e];
    }
#pragma unroll
    for (int off = 16; off > 0; off >>= 1) {
#pragma unroll
        for (int e = 0; e < NEXP; e++)
            acc[e] += __shfl_xor_sync(0xffffffffu, acc[e], off);
    }
    if (lane == 0) {
        float mx = acc[0];
#pragma unroll
        for (int e = 1; e < NEXP; e++) mx = fmaxf(mx, acc[e]);
        float p[NEXP];
#pragma unroll
        for (int e = 0; e < NEXP; e++) p[e] = __expf(acc[e] - mx);
        int i0 = 0;
#pragma unroll
        for (int e = 1; e < NEXP; e++) if (p[e] > p[i0]) i0 = e;
        int i1 = (i0 == 0) ? 1 : 0;
#pragma unroll
        for (int e = 0; e < NEXP; e++)
            if (e != i0 && p[e] > p[i1]) i1 = e;
        float s  = p[i0] + p[i1];
        float w0 = p[i0] / s, w1 = p[i1] / s;
        int t = warp;
        int pos0 = atomicAdd(&g_cnt[i0], 1);
        g_tok[i0 * T_TOKENS + pos0]  = t;
        g_slot[i0 * T_TOKENS + pos0] = 2 * t;
        g_rw[2 * t] = w0;
        int pos1 = atomicAdd(&g_cnt[i1], 1);
        g_tok[i1 * T_TOKENS + pos1]  = t;
        g_slot[i1 * T_TOKENS + pos1] = 2 * t + 1;
        g_rw[2 * t + 1] = w1;
    }
}

__global__ void zero_cnt_kernel() {
    if (threadIdx.x < NEXP) g_cnt[threadIdx.x] = 0;
}

// -------- weighted combine: out[t] = w0*y[2t] + w1*y[2t+1] ---------------
__global__ void combine_kernel(const float* __restrict__ y,
                               const float* __restrict__ rw,
                               float* __restrict__ out)
{
    const int i = blockIdx.x * blockDim.x + threadIdx.x;   // float4 index
    const int total = T_TOKENS * (DIM / 4);
    if (i >= total) return;
    const int t  = i / (DIM / 4);
    const int d4 = i % (DIM / 4);
    const float w0 = rw[2 * t], w1 = rw[2 * t + 1];
    const float4 a = ((const float4*)(y + (long long)(2 * t) * DIM))[d4];
    const float4 b = ((const float4*)(y + (long long)(2 * t + 1) * DIM))[d4];
    float4 r;
    r.x = w0 * a.x + w1 * b.x;
    r.y = w0 * a.y + w1 * b.y;
    r.z = w0 * a.z + w1 * b.z;
    r.w = w0 * a.w + w1 * b.w;
    ((float4*)out)[i] = r;
}

// -------------------------------- launch ---------------------------------
extern "C" void kernel_launch(void* const* d_in, const int* in_sizes, int n_in,
                              void* d_out, int out_size)
{
    const float* x   = (const float*)d_in[0];   // (B,S,D) = (T, D)
    const float* rw1 = (const float*)d_in[1];   // (D, 128)
    const float* rw2 = (const float*)d_in[2];   // (128, E)
    const float* W1  = (const float*)d_in[3];   // (E, D, F)
    const float* W2  = (const float*)d_in[4];   // (E, F, D)
    float* out = (float*)d_out;

    float *hidden_p, *h_p, *y_p, *rw_p;
    int *tok_p, *slot_p, *cnt_p;
    cudaGetSymbolAddress((void**)&hidden_p, g_hidden);
    cudaGetSymbolAddress((void**)&h_p,     g_h);
    cudaGetSymbolAddress((void**)&y_p,     g_y);
    cudaGetSymbolAddress((void**)&rw_p,    g_rw);
    cudaGetSymbolAddress((void**)&tok_p,   g_tok);
    cudaGetSymbolAddress((void**)&slot_p,  g_slot);
    cudaGetSymbolAddress((void**)&cnt_p,   g_cnt);

    // 1. zero per-expert counters
    zero_cnt_kernel<<<1, 32>>>();

    // 2. router hidden = silu(X @ router_w1)   [M=T, N=128, K=D]
    gemm_kernel<true><<<dim3(RH / BN, T_TOKENS / BM, 1), 256>>>(
        x, DIM, rw1, 0LL, RH, hidden_p, RH,
        (const int*)0, (const int*)0, (const int*)0, T_TOKENS, DIM);

    // 3. router logits + softmax + top-2 + gather-list build
    router_topk_kernel<<<T_TOKENS / 8, 256>>>(hidden_p, rw2);

    // 4. grouped GEMM1: h[slot] = silu(x[tok] @ W1[e])   [N=F, K=D]
    gemm_kernel<true><<<dim3(FF / BN, T_TOKENS / BM, NEXP), 256>>>(
        x, DIM, W1, (long long)DIM * FF, FF, h_p, FF,
        tok_p, slot_p, cnt_p, 0, DIM);

    // 5. grouped GEMM2: y[slot] = h[slot] @ W2[e]        [N=D, K=F]
    gemm_kernel<false><<<dim3(DIM / BN, T_TOKENS / BM, NEXP), 256>>>(
        h_p, FF, W2, (long long)FF * DIM, DIM, y_p, DIM,
        slot_p, slot_p, cnt_p, 0, FF);

    // 6. weighted combine
    combine_kernel<<<(T_TOKENS * (DIM / 4) + 255) / 256, 256>>>(y_p, rw_p, out);
}

// round 6
// speedup vs baseline: 2.6140x; 2.6140x over previous
#include <cuda_runtime.h>
#include <cstdint>

// ---------------- problem dims ----------------
#define T_TOKENS 8192
#define DIM      1024
#define FF       2048
#define NEXP     8
#define RH       128
#define NSLOTS   (T_TOKENS * 2)

// ---------------- device scratch ----------------
__device__ float g_xp[(long long)NSLOTS * DIM];           // gathered tokens (tf32-rounded)
__device__ float g_h[(long long)NSLOTS * FF];             // expert hidden (tf32-rounded)
__device__ float g_y[(long long)NSLOTS * DIM];            // expert out
__device__ float g_w1r[(long long)NEXP * DIM * FF];       // tf32-rounded W1
__device__ float g_w2r[(long long)NEXP * FF * DIM];       // tf32-rounded W2
__device__ float g_hidden[T_TOKENS * RH];
__device__ int   g_tok[NEXP * T_TOKENS];
__device__ int   g_slot[NEXP * T_TOKENS];
__device__ int   g_cnt[NEXP];
__device__ int   g_off[NEXP];
__device__ int   g_rslot[NSLOTS];
__device__ float g_rw[NSLOTS];

// ---------------- helpers ----------------
__device__ __forceinline__ uint32_t cvta_s(const void* p) {
    uint32_t a;
    asm("{ .reg .u64 t; cvta.to.shared.u64 t, %1; cvt.u32.u64 %0, t; }" : "=r"(a) : "l"(p));
    return a;
}
__device__ __forceinline__ void cp16(uint32_t s, const void* g) {
    asm volatile("cp.async.cg.shared.global [%0], [%1], 16;" :: "r"(s), "l"(g));
}
__device__ __forceinline__ uint32_t tf32r(float f) {
    uint32_t u;
    asm("cvt.rna.tf32.f32 %0, %1;" : "=r"(u) : "f"(f));
    return u;
}
__device__ __forceinline__ float silu_f(float v) { return v / (1.0f + __expf(-v)); }

__device__ __forceinline__ void mma1688(float* c, const uint32_t* a, const uint32_t* b) {
    asm volatile(
        "mma.sync.aligned.m16n8k8.row.col.f32.tf32.tf32.f32 "
        "{%0,%1,%2,%3}, {%4,%5,%6,%7}, {%8,%9}, {%0,%1,%2,%3};"
        : "+f"(c[0]), "+f"(c[1]), "+f"(c[2]), "+f"(c[3])
        : "r"(a[0]), "r"(a[1]), "r"(a[2]), "r"(a[3]), "r"(b[0]), "r"(b[1]));
}

// ---------------- grouped tf32 GEMM ----------------
// C[row, n] = A[row, k] * B_e[k, n];  rows grouped per expert via cnt/off.
#define STAGES 4
#define ASTR 36             // padded A row stride (floats)
#define BSTR 136            // padded B row stride (floats)
#define AFL  (128 * ASTR)   // 4608 floats
#define BFL  (32 * BSTR)    // 4352 floats
#define SF   (AFL + BFL)    // 8960 floats / stage
#define SBYT (SF * 4)       // 35840 bytes / stage

template <bool SILU>
__global__ __launch_bounds__(256, 1)
void mma_gemm(const float* __restrict__ A, const float* __restrict__ B,
              float* __restrict__ C, int N, int K, long long strideB,
              const int* __restrict__ cnt, const int* __restrict__ off)
{
    extern __shared__ float sm[];
    const int e = blockIdx.z;
    const int c = cnt[e], o = off[e];
    if ((int)blockIdx.y * 128 >= c) return;
    const int row0 = o + blockIdx.y * 128;
    const int mend = o + c;
    const int n0 = blockIdx.x * 128;
    const float* Bp = B + (long long)e * strideB;

    const int tid = threadIdx.x;
    const uint32_t sbase = cvta_s(sm);

    // per-thread async-copy descriptors (4 x 16B for A, 4 x 16B for B)
    const float* aSrc[4]; uint32_t aDst[4];
    const float* bSrc[4]; uint32_t bDst[4];
#pragma unroll
    for (int i = 0; i < 4; i++) {
        const int cidx = tid + i * 256;
        const int ar = cidx >> 3, ak = (cidx & 7) * 4;
        int grow = row0 + ar;
        if (grow > mend - 1) grow = mend - 1;
        aSrc[i] = A + (long long)grow * K + ak;
        aDst[i] = sbase + (uint32_t)(ar * ASTR + ak) * 4u;
        const int bk = cidx >> 5, bn = (cidx & 31) * 4;
        bSrc[i] = Bp + (long long)bk * N + n0 + bn;
        bDst[i] = sbase + (uint32_t)(AFL + bk * BSTR + bn) * 4u;
    }

    const int nk = K / 32;
    // prologue: stages 0..2
#pragma unroll
    for (int s = 0; s < 3; s++) {
#pragma unroll
        for (int i = 0; i < 4; i++) {
            cp16(aDst[i] + s * SBYT, aSrc[i] + s * 32);
            cp16(bDst[i] + s * SBYT, bSrc[i] + (long long)s * 32 * N);
        }
        asm volatile("cp.async.commit_group;" ::: "memory");
    }

    const int wid = tid >> 5, lane = tid & 31;
    const int wm = (wid & 3) * 32, wn = (wid >> 2) * 64;
    const int l4 = lane >> 2, lq = lane & 3;

    float acc[2][8][4];
#pragma unroll
    for (int mt = 0; mt < 2; mt++)
#pragma unroll
        for (int nt = 0; nt < 8; nt++)
#pragma unroll
            for (int q = 0; q < 4; q++) acc[mt][nt][q] = 0.0f;

    for (int kt = 0; kt < nk; kt++) {
        asm volatile("cp.async.wait_group 2;" ::: "memory");
        __syncthreads();
        if (kt + 3 < nk) {
            const int s = (kt + 3) & 3;
#pragma unroll
            for (int i = 0; i < 4; i++) {
                cp16(aDst[i] + s * SBYT, aSrc[i] + (kt + 3) * 32);
                cp16(bDst[i] + s * SBYT, bSrc[i] + (long long)(kt + 3) * 32 * N);
            }
        }
        asm volatile("cp.async.commit_group;" ::: "memory");

        const float* st = sm + (kt & 3) * SF;
#pragma unroll
        for (int ks = 0; ks < 4; ks++) {
            const int kk = ks * 8;
            uint32_t a[2][4], b[8][2];
#pragma unroll
            for (int mt = 0; mt < 2; mt++) {
                const float* ap = st + (wm + mt * 16 + l4) * ASTR + kk + lq;
                a[mt][0] = __float_as_uint(ap[0]);
                a[mt][1] = __float_as_uint(ap[8 * ASTR]);
                a[mt][2] = __float_as_uint(ap[4]);
                a[mt][3] = __float_as_uint(ap[8 * ASTR + 4]);
            }
#pragma unroll
            for (int nt = 0; nt < 8; nt++) {
                const float* bp = st + AFL + (kk + lq) * BSTR + wn + nt * 8 + l4;
                b[nt][0] = __float_as_uint(bp[0]);
                b[nt][1] = __float_as_uint(bp[4 * BSTR]);
            }
#pragma unroll
            for (int mt = 0; mt < 2; mt++)
#pragma unroll
                for (int nt = 0; nt < 8; nt++)
                    mma1688(acc[mt][nt], a[mt], b[nt]);
        }
    }

    // epilogue
#pragma unroll
    for (int mt = 0; mt < 2; mt++) {
#pragma unroll
        for (int half = 0; half < 2; half++) {
            const int row = row0 + wm + mt * 16 + l4 + half * 8;
            if (row < mend) {
                float* cp0 = C + (long long)row * N + n0 + wn + lq * 2;
#pragma unroll
                for (int nt = 0; nt < 8; nt++) {
                    float v0 = acc[mt][nt][half * 2 + 0];
                    float v1 = acc[mt][nt][half * 2 + 1];
                    if (SILU) {
                        v0 = __uint_as_float(tf32r(silu_f(v0)));
                        v1 = __uint_as_float(tf32r(silu_f(v1)));
                    }
                    float2 v; v.x = v0; v.y = v1;
                    *(float2*)(cp0 + nt * 8) = v;
                }
            }
        }
    }
}

// ---------------- tf32 pre-rounding of weights ----------------
__global__ void round_w_kernel(const float* __restrict__ src, float* __restrict__ dst,
                               long long n4)
{
    const long long i = (long long)blockIdx.x * blockDim.x + threadIdx.x;
    if (i >= n4) return;
    float4 v = ((const float4*)src)[i];
    v.x = __uint_as_float(tf32r(v.x));
    v.y = __uint_as_float(tf32r(v.y));
    v.z = __uint_as_float(tf32r(v.z));
    v.w = __uint_as_float(tf32r(v.w));
    ((float4*)dst)[i] = v;
}

// ---------------- router: fp32 SIMT GEMM (exact; keeps top-k faithful) ----------------
#define RBM 128
#define RBN 128
#define RBK 16
#define RTM 8
#define RTN 8
#define RPAD 4

__global__ __launch_bounds__(256, 2)
void router_gemm_kernel(const float* __restrict__ A, const float* __restrict__ B,
                        float* __restrict__ C)
{
    const int m0 = blockIdx.y * RBM;
    __shared__ float As[2][RBK][RBM + RPAD];
    __shared__ float Bs[2][RBK][RBN];
    const int tid = threadIdx.x;
    const int tm = (tid >> 4) * RTM, tn = (tid & 15) * RTN;

    const float* aPtr[2]; int aR[2], aC[2];
#pragma unroll
    for (int i = 0; i < 2; i++) {
        int lin = tid + i * 256;
        aR[i] = lin >> 2; aC[i] = (lin & 3) * 4;
        aPtr[i] = A + (long long)(m0 + aR[i]) * DIM + aC[i];
    }
    const float* bPtr[2]; int bR[2], bC[2];
#pragma unroll
    for (int i = 0; i < 2; i++) {
        int lin = tid + i * 256;
        bR[i] = lin >> 5; bC[i] = (lin & 31) * 4;
        bPtr[i] = B + (long long)bR[i] * RH + bC[i];
    }
    float acc[RTM][RTN];
#pragma unroll
    for (int i = 0; i < RTM; i++)
#pragma unroll
        for (int j = 0; j < RTN; j++) acc[i][j] = 0.0f;

    float4 av[2], bv[2];
#pragma unroll
    for (int i = 0; i < 2; i++) { av[i] = *(const float4*)aPtr[i]; bv[i] = *(const float4*)bPtr[i]; }
#pragma unroll
    for (int i = 0; i < 2; i++) {
        As[0][aC[i]+0][aR[i]] = av[i].x; As[0][aC[i]+1][aR[i]] = av[i].y;
        As[0][aC[i]+2][aR[i]] = av[i].z; As[0][aC[i]+3][aR[i]] = av[i].w;
        *(float4*)&Bs[0][bR[i]][bC[i]] = bv[i];
    }
    __syncthreads();
    const int nk = DIM / RBK;
    for (int kt = 0; kt < nk; kt++) {
        const int buf = kt & 1;
        const bool pref = (kt + 1 < nk);
        if (pref) {
            const int k0 = (kt + 1) * RBK;
#pragma unroll
            for (int i = 0; i < 2; i++) {
                av[i] = *(const float4*)(aPtr[i] + k0);
                bv[i] = *(const float4*)(bPtr[i] + (long long)k0 * RH);
            }
        }
#pragma unroll
        for (int kk = 0; kk < RBK; kk++) {
            float a[RTM], b[RTN];
#pragma unroll
            for (int i = 0; i < RTM; i++) a[i] = As[buf][kk][tm + i];
#pragma unroll
            for (int j = 0; j < RTN; j++) b[j] = Bs[buf][kk][tn + j];
#pragma unroll
            for (int i = 0; i < RTM; i++)
#pragma unroll
                for (int j = 0; j < RTN; j++) acc[i][j] += a[i] * b[j];
        }
        if (pref) {
            const int nb = buf ^ 1;
#pragma unroll
            for (int i = 0; i < 2; i++) {
                As[nb][aC[i]+0][aR[i]] = av[i].x; As[nb][aC[i]+1][aR[i]] = av[i].y;
                As[nb][aC[i]+2][aR[i]] = av[i].z; As[nb][aC[i]+3][aR[i]] = av[i].w;
                *(float4*)&Bs[nb][bR[i]][bC[i]] = bv[i];
            }
        }
        __syncthreads();
    }
#pragma unroll
    for (int i = 0; i < RTM; i++) {
        float* cp = C + (long long)(m0 + tm + i) * RH + tn;
#pragma unroll
        for (int j = 0; j < RTN; j += 4) {
            float4 v;
            v.x = silu_f(acc[i][j+0]); v.y = silu_f(acc[i][j+1]);
            v.z = silu_f(acc[i][j+2]); v.w = silu_f(acc[i][j+3]);
            *(float4*)(cp + j) = v;
        }
    }
}

__global__ void router_topk_kernel(const float* __restrict__ hidden,
                                   const float* __restrict__ w2)
{
    const int warp = (blockIdx.x * blockDim.x + threadIdx.x) >> 5;
    const int lane = threadIdx.x & 31;
    if (warp >= T_TOKENS) return;
    const float* h = hidden + warp * RH;
    float acc[NEXP];
#pragma unroll
    for (int e = 0; e < NEXP; e++) acc[e] = 0.0f;
    for (int j = lane; j < RH; j += 32) {
        const float hv = h[j];
#pragma unroll
        for (int e = 0; e < NEXP; e++) acc[e] += hv * w2[j * NEXP + e];
    }
#pragma unroll
    for (int off = 16; off > 0; off >>= 1)
#pragma unroll
        for (int e = 0; e < NEXP; e++)
            acc[e] += __shfl_xor_sync(0xffffffffu, acc[e], off);
    if (lane == 0) {
        float mx = acc[0];
#pragma unroll
        for (int e = 1; e < NEXP; e++) mx = fmaxf(mx, acc[e]);
        float p[NEXP];
#pragma unroll
        for (int e = 0; e < NEXP; e++) p[e] = __expf(acc[e] - mx);
        int i0 = 0;
#pragma unroll
        for (int e = 1; e < NEXP; e++) if (p[e] > p[i0]) i0 = e;
        int i1 = (i0 == 0) ? 1 : 0;
#pragma unroll
        for (int e = 0; e < NEXP; e++) if (e != i0 && p[e] > p[i1]) i1 = e;
        const float s = p[i0] + p[i1];
        const int t = warp;
        int pos0 = atomicAdd(&g_cnt[i0], 1);
        g_tok[i0 * T_TOKENS + pos0]  = t;
        g_slot[i0 * T_TOKENS + pos0] = 2 * t;
        g_rw[2 * t] = p[i0] / s;
        int pos1 = atomicAdd(&g_cnt[i1], 1);
        g_tok[i1 * T_TOKENS + pos1]  = t;
        g_slot[i1 * T_TOKENS + pos1] = 2 * t + 1;
        g_rw[2 * t + 1] = p[i1] / s;
    }
}

__global__ void zero_cnt_kernel() { if (threadIdx.x < NEXP) g_cnt[threadIdx.x] = 0; }

__global__ void offsets_kernel() {
    if (threadIdx.x == 0) {
        int s = 0;
        for (int e = 0; e < NEXP; e++) { g_off[e] = s; s += g_cnt[e]; }
    }
}

// gather token rows into expert-contiguous order, tf32-rounded
__global__ void dispatch_kernel(const float* __restrict__ x)
{
    const int l = blockIdx.x;
    int e = 0;
#pragma unroll
    for (int k = 1; k < NEXP; k++) if (l >= g_off[k]) e = k;
    const int p = l - g_off[e];
    const int t = g_tok[e * T_TOKENS + p];
    if (threadIdx.x == 0) g_rslot[g_slot[e * T_TOKENS + p]] = l;
    const float4* s = (const float4*)(x + (long long)t * DIM);
    float4* d = (float4*)(g_xp + (long long)l * DIM);
    const int i = threadIdx.x;   // 256 threads, DIM/4 = 256 float4
    float4 v = s[i];
    v.x = __uint_as_float(tf32r(v.x));
    v.y = __uint_as_float(tf32r(v.y));
    v.z = __uint_as_float(tf32r(v.z));
    v.w = __uint_as_float(tf32r(v.w));
    d[i] = v;
}

__global__ void combine_kernel(const float* __restrict__ y,
                               const float* __restrict__ rw,
                               const int* __restrict__ rslot,
                               float* __restrict__ out)
{
    const int i = blockIdx.x * blockDim.x + threadIdx.x;
    const int total = T_TOKENS * (DIM / 4);
    if (i >= total) return;
    const int t = i / (DIM / 4), d4 = i % (DIM / 4);
    const float w0 = rw[2 * t], w1 = rw[2 * t + 1];
    const int r0 = rslot[2 * t], r1 = rslot[2 * t + 1];
    const float4 a = ((const float4*)(y + (long long)r0 * DIM))[d4];
    const float4 b = ((const float4*)(y + (long long)r1 * DIM))[d4];
    float4 r;
    r.x = w0 * a.x + w1 * b.x;
    r.y = w0 * a.y + w1 * b.y;
    r.z = w0 * a.z + w1 * b.z;
    r.w = w0 * a.w + w1 * b.w;
    ((float4*)out)[i] = r;
}

// ---------------- host ----------------
extern "C" void kernel_launch(void* const* d_in, const int* in_sizes, int n_in,
                              void* d_out, int out_size)
{
    const float* x   = (const float*)d_in[0];
    const float* rw1 = (const float*)d_in[1];
    const float* rw2 = (const float*)d_in[2];
    const float* W1  = (const float*)d_in[3];
    const float* W2  = (const float*)d_in[4];
    float* out = (float*)d_out;

    void *xp, *hp, *yp, *w1r, *w2r, *hidp, *rwp, *rslotp, *cntp, *offp;
    cudaGetSymbolAddress(&xp, g_xp);
    cudaGetSymbolAddress(&hp, g_h);
    cudaGetSymbolAddress(&yp, g_y);
    cudaGetSymbolAddress(&w1r, g_w1r);
    cudaGetSymbolAddress(&w2r, g_w2r);
    cudaGetSymbolAddress(&hidp, g_hidden);
    cudaGetSymbolAddress(&rwp, g_rw);
    cudaGetSymbolAddress(&rslotp, g_rslot);
    cudaGetSymbolAddress(&cntp, g_cnt);
    cudaGetSymbolAddress(&offp, g_off);

    const int SMEM = STAGES * SBYT;   // 143360
    cudaFuncSetAttribute(mma_gemm<true>,
                         cudaFuncAttributeMaxDynamicSharedMemorySize, SMEM);
    cudaFuncSetAttribute(mma_gemm<false>,
                         cudaFuncAttributeMaxDynamicSharedMemorySize, SMEM);

    // 1. zero per-expert counters
    zero_cnt_kernel<<<1, 32>>>();

    // 2. pre-round weights to tf32 (unbiased rna; HW truncation would bias)
    const long long w_n4 = (long long)NEXP * DIM * FF / 4;
    round_w_kernel<<<(int)((w_n4 + 255) / 256), 256>>>(W1, (float*)w1r, w_n4);
    round_w_kernel<<<(int)((w_n4 + 255) / 256), 256>>>(W2, (float*)w2r, w_n4);

    // 3. router hidden = silu(X @ router_w1)   (exact fp32)
    router_gemm_kernel<<<dim3(1, T_TOKENS / RBM), 256>>>(x, rw1, (float*)hidp);

    // 4. router logits + softmax + top-2
    router_topk_kernel<<<T_TOKENS / 8, 256>>>((const float*)hidp, rw2);

    // 5. offsets + gather into expert-contiguous perm buffer
    offsets_kernel<<<1, 32>>>();
    dispatch_kernel<<<NSLOTS, 256>>>(x);

    // 6. grouped GEMM1: h = silu(x_perm @ W1[e])   [N=FF, K=DIM]
    mma_gemm<true><<<dim3(FF / 128, T_TOKENS / 128, NEXP), 256, SMEM>>>(
        (const float*)xp, (const float*)w1r, (float*)hp,
        FF, DIM, (long long)DIM * FF, (const int*)cntp, (const int*)offp);

    // 7. grouped GEMM2: y = h @ W2[e]              [N=DIM, K=FF]
    mma_gemm<false><<<dim3(DIM / 128, T_TOKENS / 128, NEXP), 256, SMEM>>>(
        (const float*)hp, (const float*)w2r, (float*)yp,
        DIM, FF, (long long)FF * DIM, (const int*)cntp, (const int*)offp);

    // 8. weighted combine
    combine_kernel<<<(T_TOKENS * (DIM / 4) + 255) / 256, 256>>>(
        (const float*)yp, (const float*)rwp, (const int*)rslotp, out);
}

// round 7
// speedup vs baseline: 2.7635x; 1.0572x over previous
#include <cuda_runtime.h>
#include <cstdint>

// ---------------- problem dims ----------------
#define T_TOKENS 8192
#define DIM      1024
#define FF       2048
#define NEXP     8
#define RH       128
#define NSLOTS   (T_TOKENS * 2)

// ---------------- device scratch ----------------
__device__ float g_xp[(long long)NSLOTS * DIM];           // gathered tokens (tf32-rounded)
__device__ float g_h[(long long)NSLOTS * FF];             // expert hidden (tf32-rounded)
__device__ float g_y[(long long)NSLOTS * DIM];            // expert out
__device__ float g_w1r[(long long)NEXP * DIM * FF];       // tf32-rounded W1
__device__ float g_w2r[(long long)NEXP * FF * DIM];       // tf32-rounded W2
__device__ float g_hidden[T_TOKENS * RH];
__device__ int   g_tok[NEXP * T_TOKENS];
__device__ int   g_slot[NEXP * T_TOKENS];
__device__ int   g_cnt[NEXP];
__device__ int   g_off[NEXP];
__device__ int   g_rslot[NSLOTS];
__device__ float g_rw[NSLOTS];

// ---------------- helpers ----------------
__device__ __forceinline__ uint32_t cvta_s(const void* p) {
    uint32_t a;
    asm("{ .reg .u64 t; cvta.to.shared.u64 t, %1; cvt.u32.u64 %0, t; }" : "=r"(a) : "l"(p));
    return a;
}
__device__ __forceinline__ void cp16(uint32_t s, const void* g) {
    asm volatile("cp.async.cg.shared.global [%0], [%1], 16;" :: "r"(s), "l"(g));
}
__device__ __forceinline__ uint32_t tf32r(float f) {
    uint32_t u;
    asm("cvt.rna.tf32.f32 %0, %1;" : "=r"(u) : "f"(f));
    return u;
}
__device__ __forceinline__ float silu_f(float v) { return v / (1.0f + __expf(-v)); }

__device__ __forceinline__ void mma1688(float* c, const uint32_t* a, const uint32_t* b) {
    asm volatile(
        "mma.sync.aligned.m16n8k8.row.col.f32.tf32.tf32.f32 "
        "{%0,%1,%2,%3}, {%4,%5,%6,%7}, {%8,%9}, {%0,%1,%2,%3};"
        : "+f"(c[0]), "+f"(c[1]), "+f"(c[2]), "+f"(c[3])
        : "r"(a[0]), "r"(a[1]), "r"(a[2]), "r"(a[3]), "r"(b[0]), "r"(b[1]));
}

// ---------------- grouped tf32 GEMM ----------------
// C[row, n] = A[row, k] * B_e[k, n];  rows grouped per expert via cnt/off.
#define STAGES 3
#define ASTR 36             // padded A row stride (floats)
#define BSTR 136            // padded B row stride (floats)
#define AFL  (128 * ASTR)   // 4608 floats
#define BFL  (32 * BSTR)    // 4352 floats
#define SF   (AFL + BFL)    // 8960 floats / stage
#define SBYT (SF * 4)       // 35840 bytes / stage

template <bool SILU>
__global__ __launch_bounds__(256, 2)
void mma_gemm(const float* __restrict__ A, const float* __restrict__ B,
              float* __restrict__ C, int N, int K, long long strideB,
              const int* __restrict__ cnt, const int* __restrict__ off)
{
    extern __shared__ float sm[];
    const int e = blockIdx.z;
    const int c = cnt[e], o = off[e];
    if ((int)blockIdx.y * 128 >= c) return;
    const int row0 = o + blockIdx.y * 128;
    const int mend = o + c;
    const int n0 = blockIdx.x * 128;
    const float* Bp = B + (long long)e * strideB;

    const int tid = threadIdx.x;
    const uint32_t sbase = cvta_s(sm);

    // per-thread async-copy descriptors (4 x 16B for A, 4 x 16B for B)
    const float* aSrc[4]; uint32_t aDst[4];
    const float* bSrc[4]; uint32_t bDst[4];
#pragma unroll
    for (int i = 0; i < 4; i++) {
        const int cidx = tid + i * 256;
        const int ar = cidx >> 3, ak = (cidx & 7) * 4;
        int grow = row0 + ar;
        if (grow > mend - 1) grow = mend - 1;
        aSrc[i] = A + (long long)grow * K + ak;
        aDst[i] = sbase + (uint32_t)(ar * ASTR + ak) * 4u;
        const int bk = cidx >> 5, bn = (cidx & 31) * 4;
        bSrc[i] = Bp + (long long)bk * N + n0 + bn;
        bDst[i] = sbase + (uint32_t)(AFL + bk * BSTR + bn) * 4u;
    }

    const int nk = K / 32;
    // prologue: stages 0..1
#pragma unroll
    for (int s = 0; s < 2; s++) {
#pragma unroll
        for (int i = 0; i < 4; i++) {
            cp16(aDst[i] + s * SBYT, aSrc[i] + s * 32);
            cp16(bDst[i] + s * SBYT, bSrc[i] + (long long)s * 32 * N);
        }
        asm volatile("cp.async.commit_group;" ::: "memory");
    }

    const int wid = tid >> 5, lane = tid & 31;
    const int wm = (wid & 3) * 32, wn = (wid >> 2) * 64;
    const int l4 = lane >> 2, lq = lane & 3;

    float acc[2][8][4];
#pragma unroll
    for (int mt = 0; mt < 2; mt++)
#pragma unroll
        for (int nt = 0; nt < 8; nt++)
#pragma unroll
            for (int q = 0; q < 4; q++) acc[mt][nt][q] = 0.0f;

    int rstage = 0, pstage = 2;
    for (int kt = 0; kt < nk; kt++) {
        asm volatile("cp.async.wait_group 1;" ::: "memory");
        __syncthreads();
        if (kt + 2 < nk) {
#pragma unroll
            for (int i = 0; i < 4; i++) {
                cp16(aDst[i] + pstage * SBYT, aSrc[i] + (kt + 2) * 32);
                cp16(bDst[i] + pstage * SBYT, bSrc[i] + (long long)(kt + 2) * 32 * N);
            }
        }
        asm volatile("cp.async.commit_group;" ::: "memory");

        const float* st = sm + rstage * SF;
#pragma unroll
        for (int ks = 0; ks < 4; ks++) {
            const int kk = ks * 8;
            uint32_t a[2][4], b[8][2];
#pragma unroll
            for (int mt = 0; mt < 2; mt++) {
                const float* ap = st + (wm + mt * 16 + l4) * ASTR + kk + lq;
                a[mt][0] = __float_as_uint(ap[0]);
                a[mt][1] = __float_as_uint(ap[8 * ASTR]);
                a[mt][2] = __float_as_uint(ap[4]);
                a[mt][3] = __float_as_uint(ap[8 * ASTR + 4]);
            }
#pragma unroll
            for (int nt = 0; nt < 8; nt++) {
                const float* bp = st + AFL + (kk + lq) * BSTR + wn + nt * 8 + l4;
                b[nt][0] = __float_as_uint(bp[0]);
                b[nt][1] = __float_as_uint(bp[4 * BSTR]);
            }
#pragma unroll
            for (int mt = 0; mt < 2; mt++)
#pragma unroll
                for (int nt = 0; nt < 8; nt++)
                    mma1688(acc[mt][nt], a[mt], b[nt]);
        }
        if (++rstage == STAGES) rstage = 0;
        if (++pstage == STAGES) pstage = 0;
    }

    // epilogue
#pragma unroll
    for (int mt = 0; mt < 2; mt++) {
#pragma unroll
        for (int half = 0; half < 2; half++) {
            const int row = row0 + wm + mt * 16 + l4 + half * 8;
            if (row < mend) {
                float* cp0 = C + (long long)row * N + n0 + wn + lq * 2;
#pragma unroll
                for (int nt = 0; nt < 8; nt++) {
                    float v0 = acc[mt][nt][half * 2 + 0];
                    float v1 = acc[mt][nt][half * 2 + 1];
                    if (SILU) {
                        v0 = __uint_as_float(tf32r(silu_f(v0)));
                        v1 = __uint_as_float(tf32r(silu_f(v1)));
                    }
                    float2 v; v.x = v0; v.y = v1;
                    *(float2*)(cp0 + nt * 8) = v;
                }
            }
        }
    }
}

// ---------------- tf32 pre-rounding of weights ----------------
__global__ void round_w_kernel(const float* __restrict__ src, float* __restrict__ dst,
                               long long n4)
{
    const long long i = (long long)blockIdx.x * blockDim.x + threadIdx.x;
    if (i >= n4) return;
    float4 v = ((const float4*)src)[i];
    v.x = __uint_as_float(tf32r(v.x));
    v.y = __uint_as_float(tf32r(v.y));
    v.z = __uint_as_float(tf32r(v.z));
    v.w = __uint_as_float(tf32r(v.w));
    ((float4*)dst)[i] = v;
}

// ---------------- router: fp32 SIMT GEMM (exact; keeps top-k faithful) ----------------
// BM=64 -> grid (1, 128) = full wave on 148 SMs
#define RBM 64
#define RBN 128
#define RBK 16
#define RTM 4
#define RTN 8
#define RPAD 4

__global__ __launch_bounds__(256, 3)
void router_gemm_kernel(const float* __restrict__ A, const float* __restrict__ B,
                        float* __restrict__ C)
{
    const int m0 = blockIdx.y * RBM;
    __shared__ float As[2][RBK][RBM + RPAD];
    __shared__ float Bs[2][RBK][RBN];
    const int tid = threadIdx.x;
    const int tm = (tid >> 4) * RTM, tn = (tid & 15) * RTN;

    // A loader: 64x16 = 256 float4 -> 1 per thread
    const int aR = tid >> 2, aC = (tid & 3) * 4;
    const float* aPtr = A + (long long)(m0 + aR) * DIM + aC;
    // B loader: 16x128 = 512 float4 -> 2 per thread
    const float* bPtr[2]; int bR[2], bC[2];
#pragma unroll
    for (int i = 0; i < 2; i++) {
        int lin = tid + i * 256;
        bR[i] = lin >> 5; bC[i] = (lin & 31) * 4;
        bPtr[i] = B + (long long)bR[i] * RH + bC[i];
    }
    float acc[RTM][RTN];
#pragma unroll
    for (int i = 0; i < RTM; i++)
#pragma unroll
        for (int j = 0; j < RTN; j++) acc[i][j] = 0.0f;

    float4 av, bv[2];
    av = *(const float4*)aPtr;
#pragma unroll
    for (int i = 0; i < 2; i++) bv[i] = *(const float4*)bPtr[i];
    As[0][aC+0][aR] = av.x; As[0][aC+1][aR] = av.y;
    As[0][aC+2][aR] = av.z; As[0][aC+3][aR] = av.w;
#pragma unroll
    for (int i = 0; i < 2; i++) *(float4*)&Bs[0][bR[i]][bC[i]] = bv[i];
    __syncthreads();

    const int nk = DIM / RBK;
    for (int kt = 0; kt < nk; kt++) {
        const int buf = kt & 1;
        const bool pref = (kt + 1 < nk);
        if (pref) {
            const int k0 = (kt + 1) * RBK;
            av = *(const float4*)(aPtr + k0);
#pragma unroll
            for (int i = 0; i < 2; i++)
                bv[i] = *(const float4*)(bPtr[i] + (long long)k0 * RH);
        }
#pragma unroll
        for (int kk = 0; kk < RBK; kk++) {
            float a[RTM], b[RTN];
#pragma unroll
            for (int i = 0; i < RTM; i++) a[i] = As[buf][kk][tm + i];
#pragma unroll
            for (int j = 0; j < RTN; j++) b[j] = Bs[buf][kk][tn + j];
#pragma unroll
            for (int i = 0; i < RTM; i++)
#pragma unroll
                for (int j = 0; j < RTN; j++) acc[i][j] += a[i] * b[j];
        }
        if (pref) {
            const int nb = buf ^ 1;
            As[nb][aC+0][aR] = av.x; As[nb][aC+1][aR] = av.y;
            As[nb][aC+2][aR] = av.z; As[nb][aC+3][aR] = av.w;
#pragma unroll
            for (int i = 0; i < 2; i++) *(float4*)&Bs[nb][bR[i]][bC[i]] = bv[i];
        }
        __syncthreads();
    }
#pragma unroll
    for (int i = 0; i < RTM; i++) {
        float* cp = C + (long long)(m0 + tm + i) * RH + tn;
#pragma unroll
        for (int j = 0; j < RTN; j += 4) {
            float4 v;
            v.x = silu_f(acc[i][j+0]); v.y = silu_f(acc[i][j+1]);
            v.z = silu_f(acc[i][j+2]); v.w = silu_f(acc[i][j+3]);
            *(float4*)(cp + j) = v;
        }
    }
}

__global__ void router_topk_kernel(const float* __restrict__ hidden,
                                   const float* __restrict__ w2)
{
    const int warp = (blockIdx.x * blockDim.x + threadIdx.x) >> 5;
    const int lane = threadIdx.x & 31;
    if (warp >= T_TOKENS) return;
    const float* h = hidden + warp * RH;
    float acc[NEXP];
#pragma unroll
    for (int e = 0; e < NEXP; e++) acc[e] = 0.0f;
    for (int j = lane; j < RH; j += 32) {
        const float hv = h[j];
#pragma unroll
        for (int e = 0; e < NEXP; e++) acc[e] += hv * w2[j * NEXP + e];
    }
#pragma unroll
    for (int off = 16; off > 0; off >>= 1)
#pragma unroll
        for (int e = 0; e < NEXP; e++)
            acc[e] += __shfl_xor_sync(0xffffffffu, acc[e], off);
    if (lane == 0) {
        float mx = acc[0];
#pragma unroll
        for (int e = 1; e < NEXP; e++) mx = fmaxf(mx, acc[e]);
        float p[NEXP];
#pragma unroll
        for (int e = 0; e < NEXP; e++) p[e] = __expf(acc[e] - mx);
        int i0 = 0;
#pragma unroll
        for (int e = 1; e < NEXP; e++) if (p[e] > p[i0]) i0 = e;
        int i1 = (i0 == 0) ? 1 : 0;
#pragma unroll
        for (int e = 0; e < NEXP; e++) if (e != i0 && p[e] > p[i1]) i1 = e;
        const float s = p[i0] + p[i1];
        const int t = warp;
        int pos0 = atomicAdd(&g_cnt[i0], 1);
        g_tok[i0 * T_TOKENS + pos0]  = t;
        g_slot[i0 * T_TOKENS + pos0] = 2 * t;
        g_rw[2 * t] = p[i0] / s;
        int pos1 = atomicAdd(&g_cnt[i1], 1);
        g_tok[i1 * T_TOKENS + pos1]  = t;
        g_slot[i1 * T_TOKENS + pos1] = 2 * t + 1;
        g_rw[2 * t + 1] = p[i1] / s;
    }
}

__global__ void zero_cnt_kernel() { if (threadIdx.x < NEXP) g_cnt[threadIdx.x] = 0; }

__global__ void offsets_kernel() {
    if (threadIdx.x == 0) {
        int s = 0;
        for (int e = 0; e < NEXP; e++) { g_off[e] = s; s += g_cnt[e]; }
    }
}

// gather token rows into expert-contiguous order, tf32-rounded
__global__ void dispatch_kernel(const float* __restrict__ x)
{
    const int l = blockIdx.x;
    int e = 0;
#pragma unroll
    for (int k = 1; k < NEXP; k++) if (l >= g_off[k]) e = k;
    const int p = l - g_off[e];
    const int t = g_tok[e * T_TOKENS + p];
    if (threadIdx.x == 0) g_rslot[g_slot[e * T_TOKENS + p]] = l;
    const float4* s = (const float4*)(x + (long long)t * DIM);
    float4* d = (float4*)(g_xp + (long long)l * DIM);
    const int i = threadIdx.x;   // 256 threads, DIM/4 = 256 float4
    float4 v = s[i];
    v.x = __uint_as_float(tf32r(v.x));
    v.y = __uint_as_float(tf32r(v.y));
    v.z = __uint_as_float(tf32r(v.z));
    v.w = __uint_as_float(tf32r(v.w));
    d[i] = v;
}

__global__ void combine_kernel(const float* __restrict__ y,
                               const float* __restrict__ rw,
                               const int* __restrict__ rslot,
                               float* __restrict__ out)
{
    const int i = blockIdx.x * blockDim.x + threadIdx.x;
    const int total = T_TOKENS * (DIM / 4);
    if (i >= total) return;
    const int t = i / (DIM / 4), d4 = i % (DIM / 4);
    const float w0 = rw[2 * t], w1 = rw[2 * t + 1];
    const int r0 = rslot[2 * t], r1 = rslot[2 * t + 1];
    const float4 a = ((const float4*)(y + (long long)r0 * DIM))[d4];
    const float4 b = ((const float4*)(y + (long long)r1 * DIM))[d4];
    float4 r;
    r.x = w0 * a.x + w1 * b.x;
    r.y = w0 * a.y + w1 * b.y;
    r.z = w0 * a.z + w1 * b.z;
    r.w = w0 * a.w + w1 * b.w;
    ((float4*)out)[i] = r;
}

// ---------------- host ----------------
extern "C" void kernel_launch(void* const* d_in, const int* in_sizes, int n_in,
                              void* d_out, int out_size)
{
    const float* x   = (const float*)d_in[0];
    const float* rw1 = (const float*)d_in[1];
    const float* rw2 = (const float*)d_in[2];
    const float* W1  = (const float*)d_in[3];
    const float* W2  = (const float*)d_in[4];
    float* out = (float*)d_out;

    void *xp, *hp, *yp, *w1r, *w2r, *hidp, *rwp, *rslotp, *cntp, *offp;
    cudaGetSymbolAddress(&xp, g_xp);
    cudaGetSymbolAddress(&hp, g_h);
    cudaGetSymbolAddress(&yp, g_y);
    cudaGetSymbolAddress(&w1r, g_w1r);
    cudaGetSymbolAddress(&w2r, g_w2r);
    cudaGetSymbolAddress(&hidp, g_hidden);
    cudaGetSymbolAddress(&rwp, g_rw);
    cudaGetSymbolAddress(&rslotp, g_rslot);
    cudaGetSymbolAddress(&cntp, g_cnt);
    cudaGetSymbolAddress(&offp, g_off);

    const int SMEM = STAGES * SBYT;   // 107520
    cudaFuncSetAttribute(mma_gemm<true>,
                         cudaFuncAttributeMaxDynamicSharedMemorySize, SMEM);
    cudaFuncSetAttribute(mma_gemm<false>,
                         cudaFuncAttributeMaxDynamicSharedMemorySize, SMEM);

    // side stream for weight pre-rounding (fork/join via events; capture-legal)
    cudaStream_t s1;
    cudaStreamCreate(&s1);
    cudaEvent_t e0, e1;
    cudaEventCreateWithFlags(&e0, cudaEventDisableTiming);
    cudaEventCreateWithFlags(&e1, cudaEventDisableTiming);

    // 1. zero per-expert counters (main stream)
    zero_cnt_kernel<<<1, 32>>>();
    cudaEventRecord(e0, 0);
    cudaStreamWaitEvent(s1, e0, 0);

    // 2. pre-round weights to tf32 on side stream (overlaps router chain)
    const long long w_n4 = (long long)NEXP * DIM * FF / 4;
    round_w_kernel<<<(int)((w_n4 + 255) / 256), 256, 0, s1>>>(W1, (float*)w1r, w_n4);
    round_w_kernel<<<(int)((w_n4 + 255) / 256), 256, 0, s1>>>(W2, (float*)w2r, w_n4);
    cudaEventRecord(e1, s1);

    // 3. router hidden = silu(X @ router_w1)   (exact fp32)
    router_gemm_kernel<<<dim3(1, T_TOKENS / RBM), 256>>>(x, rw1, (float*)hidp);

    // 4. router logits + softmax + top-2
    router_topk_kernel<<<T_TOKENS / 8, 256>>>((const float*)hidp, rw2);

    // 5. offsets + gather into expert-contiguous perm buffer
    offsets_kernel<<<1, 32>>>();
    dispatch_kernel<<<NSLOTS, 256>>>(x);

    // join: weights rounded before grouped GEMMs
    cudaStreamWaitEvent(0, e1, 0);

    // 6. grouped GEMM1: h = silu(x_perm @ W1[e])   [N=FF, K=DIM]
    mma_gemm<true><<<dim3(FF / 128, T_TOKENS / 128, NEXP), 256, SMEM>>>(
        (const float*)xp, (const float*)w1r, (float*)hp,
        FF, DIM, (long long)DIM * FF, (const int*)cntp, (const int*)offp);

    // 7. grouped GEMM2: y = h @ W2[e]              [N=DIM, K=FF]
    mma_gemm<false><<<dim3(DIM / 128, T_TOKENS / 128, NEXP), 256, SMEM>>>(
        (const float*)hp, (const float*)w2r, (float*)yp,
        DIM, FF, (long long)FF * DIM, (const int*)cntp, (const int*)offp);

    // 8. weighted combine
    combine_kernel<<<(T_TOKENS * (DIM / 4) + 255) / 256, 256>>>(
        (const float*)yp, (const float*)rwp, (const int*)rslotp, out);
}

// round 8
// speedup vs baseline: 4.7598x; 1.7224x over previous
#include <cuda_runtime.h>
#include <cuda_fp16.h>
#include <cstdint>

// ---------------- problem dims ----------------
#define T_TOKENS 8192
#define DIM      1024
#define FF       2048
#define NEXP     8
#define RH       128
#define NSLOTS   (T_TOKENS * 2)
#define KSPLIT   4

// ---------------- device scratch ----------------
__device__ __half g_xp[(long long)NSLOTS * DIM];            // gathered tokens (half)
__device__ __half g_h[(long long)NSLOTS * FF];              // expert hidden (half)
__device__ float  g_y[(long long)NSLOTS * DIM];             // expert out
__device__ __half g_w1t[(long long)NEXP * FF * DIM];        // W1^T [e][f][d] half
__device__ __half g_w2t[(long long)NEXP * DIM * FF];        // W2^T [e][d][f] half
__device__ float  g_rpart[(long long)KSPLIT * T_TOKENS * RH];
__device__ float  g_hidden[T_TOKENS * RH];
__device__ int    g_tok[NEXP * T_TOKENS];
__device__ int    g_slot[NEXP * T_TOKENS];
__device__ int    g_cnt[NEXP];
__device__ int    g_off[NEXP];
__device__ int    g_rslot[NSLOTS];
__device__ float  g_rw[NSLOTS];

// ---------------- helpers ----------------
__device__ __forceinline__ uint32_t cvta_s(const void* p) {
    uint32_t a;
    asm("{ .reg .u64 t; cvta.to.shared.u64 t, %1; cvt.u32.u64 %0, t; }" : "=r"(a) : "l"(p));
    return a;
}
__device__ __forceinline__ void cp16(uint32_t s, const void* g) {
    asm volatile("cp.async.cg.shared.global [%0], [%1], 16;" :: "r"(s), "l"(g));
}
__device__ __forceinline__ uint32_t tf32r(float f) {
    uint32_t u;
    asm("cvt.rna.tf32.f32 %0, %1;" : "=r"(u) : "f"(f));
    return u;
}
__device__ __forceinline__ void tf32split(float v, uint32_t& hi, uint32_t& lo) {
    hi = tf32r(v);
    lo = tf32r(v - __uint_as_float(hi));
}
__device__ __forceinline__ float silu_f(float v) { return v / (1.0f + __expf(-v)); }

__device__ __forceinline__ void mma1688(float* c, const uint32_t* a, const uint32_t* b) {
    asm volatile(
        "mma.sync.aligned.m16n8k8.row.col.f32.tf32.tf32.f32 "
        "{%0,%1,%2,%3}, {%4,%5,%6,%7}, {%8,%9}, {%0,%1,%2,%3};"
        : "+f"(c[0]), "+f"(c[1]), "+f"(c[2]), "+f"(c[3])
        : "r"(a[0]), "r"(a[1]), "r"(a[2]), "r"(a[3]), "r"(b[0]), "r"(b[1]));
}
__device__ __forceinline__ void mma16816(float* c, const uint32_t* a, const uint32_t* b) {
    asm volatile(
        "mma.sync.aligned.m16n8k16.row.col.f32.f16.f16.f32 "
        "{%0,%1,%2,%3}, {%4,%5,%6,%7}, {%8,%9}, {%0,%1,%2,%3};"
        : "+f"(c[0]), "+f"(c[1]), "+f"(c[2]), "+f"(c[3])
        : "r"(a[0]), "r"(a[1]), "r"(a[2]), "r"(a[3]), "r"(b[0]), "r"(b[1]));
}

// ================ fp16 grouped GEMM (m16n8k16) ================
// C[row, n] = A[row, k] * Bt_e[n, k];  A row-major half, Bt n-major half.
#define HSTAGES 4
#define ASTR_H  40                  // halves per A row (32 + 8 pad)
#define A_HALFS (128 * ASTR_H)      // 5120
#define B_HALFS (128 * ASTR_H)      // 5120
#define SFH     (A_HALFS + B_HALFS) // 10240 halves / stage
#define SBYT_H  (SFH * 2)           // 20480 bytes / stage

template <bool SILU>
__global__ __launch_bounds__(256, 2)
void hgemm(const __half* __restrict__ A, const __half* __restrict__ Bt,
           __half* __restrict__ Ch, float* __restrict__ Cf,
           int N, int K,
           const int* __restrict__ cnt, const int* __restrict__ off)
{
    extern __shared__ __half smh[];
    const int e = blockIdx.z;
    const int c = cnt[e], o = off[e];
    if ((int)blockIdx.y * 128 >= c) return;
    const int row0 = o + blockIdx.y * 128;
    const int mend = o + c;
    const int n0 = blockIdx.x * 128;
    const __half* Bp = Bt + (long long)e * N * K;

    const int tid = threadIdx.x;
    const uint32_t sbase = cvta_s(smh);

    // loaders: 2 x 16B for A, 2 x 16B for B per thread
    const __half* aSrc[2]; uint32_t aDst[2];
    const __half* bSrc[2]; uint32_t bDst[2];
#pragma unroll
    for (int i = 0; i < 2; i++) {
        const int idx = tid + i * 256;          // 0..511
        const int ar = idx >> 2, ac = idx & 3;  // row 0..127, 16B chunk 0..3
        int grow = row0 + ar;
        if (grow > mend - 1) grow = mend - 1;
        aSrc[i] = A + (long long)grow * K + ac * 8;
        aDst[i] = sbase + (uint32_t)(ar * 80 + ac * 16);
        const int br = idx >> 2, bc = idx & 3;
        bSrc[i] = Bp + (long long)(n0 + br) * K + bc * 8;
        bDst[i] = sbase + (uint32_t)(A_HALFS * 2 + br * 80 + bc * 16);
    }

    const int nk = K / 32;
    // prologue: stages 0..2
#pragma unroll
    for (int s = 0; s < 3; s++) {
#pragma unroll
        for (int i = 0; i < 2; i++) {
            cp16(aDst[i] + s * SBYT_H, aSrc[i] + s * 32);
            cp16(bDst[i] + s * SBYT_H, bSrc[i] + s * 32);
        }
        asm volatile("cp.async.commit_group;" ::: "memory");
    }

    const int wid = tid >> 5, lane = tid & 31;
    const int wm = (wid & 3) * 32, wn = (wid >> 2) * 64;
    const int l4 = lane >> 2, lq = lane & 3;

    float acc[2][8][4];
#pragma unroll
    for (int mt = 0; mt < 2; mt++)
#pragma unroll
        for (int nt = 0; nt < 8; nt++)
#pragma unroll
            for (int q = 0; q < 4; q++) acc[mt][nt][q] = 0.0f;

    for (int kt = 0; kt < nk; kt++) {
        asm volatile("cp.async.wait_group 2;" ::: "memory");
        __syncthreads();
        if (kt + 3 < nk) {
            const int s = (kt + 3) & 3;
#pragma unroll
            for (int i = 0; i < 2; i++) {
                cp16(aDst[i] + s * SBYT_H, aSrc[i] + (kt + 3) * 32);
                cp16(bDst[i] + s * SBYT_H, bSrc[i] + (kt + 3) * 32);
            }
        }
        asm volatile("cp.async.commit_group;" ::: "memory");

        const __half* st = smh + (kt & 3) * SFH;
#pragma unroll
        for (int ks = 0; ks < 2; ks++) {
            const int kk = ks * 16;
            uint32_t a[2][4], b[8][2];
#pragma unroll
            for (int mt = 0; mt < 2; mt++) {
                const __half* ap = st + (wm + mt * 16 + l4) * ASTR_H + kk + 2 * lq;
                a[mt][0] = *(const uint32_t*)(ap);
                a[mt][1] = *(const uint32_t*)(ap + 8 * ASTR_H);
                a[mt][2] = *(const uint32_t*)(ap + 8);
                a[mt][3] = *(const uint32_t*)(ap + 8 * ASTR_H + 8);
            }
#pragma unroll
            for (int nt = 0; nt < 8; nt++) {
                const __half* bp = st + A_HALFS + (wn + nt * 8 + l4) * ASTR_H + kk + 2 * lq;
                b[nt][0] = *(const uint32_t*)(bp);
                b[nt][1] = *(const uint32_t*)(bp + 8);
            }
#pragma unroll
            for (int mt = 0; mt < 2; mt++)
#pragma unroll
                for (int nt = 0; nt < 8; nt++)
                    mma16816(acc[mt][nt], a[mt], b[nt]);
        }
    }

    // epilogue
#pragma unroll
    for (int mt = 0; mt < 2; mt++) {
#pragma unroll
        for (int hr = 0; hr < 2; hr++) {
            const int row = row0 + wm + mt * 16 + l4 + hr * 8;
            if (row < mend) {
                if (SILU) {
                    __half* cp0 = Ch + (long long)row * N + n0 + wn + lq * 2;
#pragma unroll
                    for (int nt = 0; nt < 8; nt++) {
                        const float v0 = silu_f(acc[mt][nt][hr * 2 + 0]);
                        const float v1 = silu_f(acc[mt][nt][hr * 2 + 1]);
                        *(__half2*)(cp0 + nt * 8) = __floats2half2_rn(v0, v1);
                    }
                } else {
                    float* cp0 = Cf + (long long)row * N + n0 + wn + lq * 2;
#pragma unroll
                    for (int nt = 0; nt < 8; nt++) {
                        float2 v;
                        v.x = acc[mt][nt][hr * 2 + 0];
                        v.y = acc[mt][nt][hr * 2 + 1];
                        *(float2*)(cp0 + nt * 8) = v;
                    }
                }
            }
        }
    }
}

// ================ router hidden: 3xtf32 MMA with K-split ================
#define RSTAGES 3
#define ASTR 36
#define BSTR 136
#define AFL  (128 * ASTR)
#define BFL  (32 * BSTR)
#define SF   (AFL + BFL)
#define SBYT (SF * 4)

__global__ __launch_bounds__(256)
void router_mma(const float* __restrict__ x, const float* __restrict__ rw1,
                float* __restrict__ part)
{
    extern __shared__ float sm[];
    const int kz = blockIdx.x;                 // K-split index
    const int row0 = blockIdx.y * 128;
    const int kbase = kz * (DIM / KSPLIT);     // 256

    const int tid = threadIdx.x;
    const uint32_t sbase = cvta_s(sm);

    const float* aSrc[4]; uint32_t aDst[4];
    const float* bSrc[4]; uint32_t bDst[4];
#pragma unroll
    for (int i = 0; i < 4; i++) {
        const int cidx = tid + i * 256;
        const int ar = cidx >> 3, ak = (cidx & 7) * 4;
        aSrc[i] = x + (long long)(row0 + ar) * DIM + kbase + ak;
        aDst[i] = sbase + (uint32_t)(ar * ASTR + ak) * 4u;
        const int bk = cidx >> 5, bn = (cidx & 31) * 4;
        bSrc[i] = rw1 + (long long)(kbase + bk) * RH + bn;
        bDst[i] = sbase + (uint32_t)(AFL + bk * BSTR + bn) * 4u;
    }

    const int nk = (DIM / KSPLIT) / 32;        // 8
#pragma unroll
    for (int s = 0; s < 2; s++) {
#pragma unroll
        for (int i = 0; i < 4; i++) {
            cp16(aDst[i] + s * SBYT, aSrc[i] + s * 32);
            cp16(bDst[i] + s * SBYT, bSrc[i] + (long long)s * 32 * RH);
        }
        asm volatile("cp.async.commit_group;" ::: "memory");
    }

    const int wid = tid >> 5, lane = tid & 31;
    const int wm = (wid & 3) * 32, wn = (wid >> 2) * 64;
    const int l4 = lane >> 2, lq = lane & 3;

    float acc[2][8][4];
#pragma unroll
    for (int mt = 0; mt < 2; mt++)
#pragma unroll
        for (int nt = 0; nt < 8; nt++)
#pragma unroll
            for (int q = 0; q < 4; q++) acc[mt][nt][q] = 0.0f;

    int rstage = 0, pstage = 2;
    for (int kt = 0; kt < nk; kt++) {
        asm volatile("cp.async.wait_group 1;" ::: "memory");
        __syncthreads();
        if (kt + 2 < nk) {
#pragma unroll
            for (int i = 0; i < 4; i++) {
                cp16(aDst[i] + pstage * SBYT, aSrc[i] + (kt + 2) * 32);
                cp16(bDst[i] + pstage * SBYT, bSrc[i] + (long long)(kt + 2) * 32 * RH);
            }
        }
        asm volatile("cp.async.commit_group;" ::: "memory");

        const float* st = sm + rstage * SF;
#pragma unroll
        for (int ks = 0; ks < 4; ks++) {
            const int kk = ks * 8;
            uint32_t ah[2][4], al[2][4], bh[8][2], bl[8][2];
#pragma unroll
            for (int mt = 0; mt < 2; mt++) {
                const float* ap = st + (wm + mt * 16 + l4) * ASTR + kk + lq;
                tf32split(ap[0],            ah[mt][0], al[mt][0]);
                tf32split(ap[8 * ASTR],     ah[mt][1], al[mt][1]);
                tf32split(ap[4],            ah[mt][2], al[mt][2]);
                tf32split(ap[8 * ASTR + 4], ah[mt][3], al[mt][3]);
            }
#pragma unroll
            for (int nt = 0; nt < 8; nt++) {
                const float* bp = st + AFL + (kk + lq) * BSTR + wn + nt * 8 + l4;
                tf32split(bp[0],        bh[nt][0], bl[nt][0]);
                tf32split(bp[4 * BSTR], bh[nt][1], bl[nt][1]);
            }
#pragma unroll
            for (int mt = 0; mt < 2; mt++)
#pragma unroll
                for (int nt = 0; nt < 8; nt++) {
                    mma1688(acc[mt][nt], ah[mt], bh[nt]);
                    mma1688(acc[mt][nt], ah[mt], bl[nt]);
                    mma1688(acc[mt][nt], al[mt], bh[nt]);
                }
        }
        if (++rstage == RSTAGES) rstage = 0;
        if (++pstage == RSTAGES) pstage = 0;
    }

    float* base = part + (long long)kz * T_TOKENS * RH;
#pragma unroll
    for (int mt = 0; mt < 2; mt++) {
#pragma unroll
        for (int hr = 0; hr < 2; hr++) {
            const int row = row0 + wm + mt * 16 + l4 + hr * 8;
            float* cp0 = base + (long long)row * RH + wn + lq * 2;
#pragma unroll
            for (int nt = 0; nt < 8; nt++) {
                float2 v;
                v.x = acc[mt][nt][hr * 2 + 0];
                v.y = acc[mt][nt][hr * 2 + 1];
                *(float2*)(cp0 + nt * 8) = v;
            }
        }
    }
}

__global__ void reduce_silu_kernel(const float* __restrict__ part,
                                   float* __restrict__ hid)
{
    const int i = blockIdx.x * blockDim.x + threadIdx.x;
    const int total = T_TOKENS * RH / 4;
    if (i >= total) return;
    const long long stride = (long long)T_TOKENS * RH / 4;
    float4 s = ((const float4*)part)[i];
#pragma unroll
    for (int kz = 1; kz < KSPLIT; kz++) {
        const float4 v = ((const float4*)part)[i + kz * stride];
        s.x += v.x; s.y += v.y; s.z += v.z; s.w += v.w;
    }
    s.x = silu_f(s.x); s.y = silu_f(s.y); s.z = silu_f(s.z); s.w = silu_f(s.w);
    ((float4*)hid)[i] = s;
}

// ---------------- weight transpose + fp16 convert ----------------
// src [e][R][C] fp32 -> dst [e][C][R] half
__global__ void transpose_half_kernel(const float* __restrict__ src,
                                      __half* __restrict__ dst, int R, int C)
{
    __shared__ float tile[32][33];
    const int e = blockIdx.z;
    const float* s = src + (long long)e * R * C;
    __half* d = dst + (long long)e * R * C;
    const int c0 = blockIdx.x * 32, r0 = blockIdx.y * 32;
    const int tx = threadIdx.x, ty = threadIdx.y;
#pragma unroll
    for (int i = 0; i < 32; i += 8)
        tile[ty + i][tx] = s[(long long)(r0 + ty + i) * C + c0 + tx];
    __syncthreads();
#pragma unroll
    for (int i = 0; i < 32; i += 8)
        d[(long long)(c0 + ty + i) * R + r0 + tx] = __float2half_rn(tile[tx][ty + i]);
}

// ---------------- routing ----------------
__global__ void router_topk_kernel(const float* __restrict__ hidden,
                                   const float* __restrict__ w2)
{
    const int warp = (blockIdx.x * blockDim.x + threadIdx.x) >> 5;
    const int lane = threadIdx.x & 31;
    if (warp >= T_TOKENS) return;
    const float* h = hidden + warp * RH;
    float acc[NEXP];
#pragma unroll
    for (int e = 0; e < NEXP; e++) acc[e] = 0.0f;
    for (int j = lane; j < RH; j += 32) {
        const float hv = h[j];
#pragma unroll
        for (int e = 0; e < NEXP; e++) acc[e] += hv * w2[j * NEXP + e];
    }
#pragma unroll
    for (int off = 16; off > 0; off >>= 1)
#pragma unroll
        for (int e = 0; e < NEXP; e++)
            acc[e] += __shfl_xor_sync(0xffffffffu, acc[e], off);
    if (lane == 0) {
        float mx = acc[0];
#pragma unroll
        for (int e = 1; e < NEXP; e++) mx = fmaxf(mx, acc[e]);
        float p[NEXP];
#pragma unroll
        for (int e = 0; e < NEXP; e++) p[e] = __expf(acc[e] - mx);
        int i0 = 0;
#pragma unroll
        for (int e = 1; e < NEXP; e++) if (p[e] > p[i0]) i0 = e;
        int i1 = (i0 == 0) ? 1 : 0;
#pragma unroll
        for (int e = 0; e < NEXP; e++) if (e != i0 && p[e] > p[i1]) i1 = e;
        const float s = p[i0] + p[i1];
        const int t = warp;
        int pos0 = atomicAdd(&g_cnt[i0], 1);
        g_tok[i0 * T_TOKENS + pos0]  = t;
        g_slot[i0 * T_TOKENS + pos0] = 2 * t;
        g_rw[2 * t] = p[i0] / s;
        int pos1 = atomicAdd(&g_cnt[i1], 1);
        g_tok[i1 * T_TOKENS + pos1]  = t;
        g_slot[i1 * T_TOKENS + pos1] = 2 * t + 1;
        g_rw[2 * t + 1] = p[i1] / s;
    }
}

__global__ void zero_cnt_kernel() { if (threadIdx.x < NEXP) g_cnt[threadIdx.x] = 0; }

__global__ void offsets_kernel() {
    if (threadIdx.x == 0) {
        int s = 0;
        for (int e = 0; e < NEXP; e++) { g_off[e] = s; s += g_cnt[e]; }
    }
}

// gather token rows -> expert-contiguous half buffer
__global__ void dispatch_kernel(const float* __restrict__ x)
{
    const int l = blockIdx.x;
    int e = 0;
#pragma unroll
    for (int k = 1; k < NEXP; k++) if (l >= g_off[k]) e = k;
    const int p = l - g_off[e];
    const int t = g_tok[e * T_TOKENS + p];
    if (threadIdx.x == 0) g_rslot[g_slot[e * T_TOKENS + p]] = l;
    const float4* s = (const float4*)(x + (long long)t * DIM);
    uint2* d = (uint2*)(g_xp + (long long)l * DIM);
    const int i = threadIdx.x;                 // 256 threads, DIM/4 float4
    const float4 v = s[i];
    const __half2 h0 = __floats2half2_rn(v.x, v.y);
    const __half2 h1 = __floats2half2_rn(v.z, v.w);
    uint2 u;
    u.x = *(const uint32_t*)&h0;
    u.y = *(const uint32_t*)&h1;
    d[i] = u;
}

__global__ void combine_kernel(const float* __restrict__ y,
                               const float* __restrict__ rw,
                               const int* __restrict__ rslot,
                               float* __restrict__ out)
{
    const int i = blockIdx.x * blockDim.x + threadIdx.x;
    const int total = T_TOKENS * (DIM / 4);
    if (i >= total) return;
    const int t = i / (DIM / 4), d4 = i % (DIM / 4);
    const float w0 = rw[2 * t], w1 = rw[2 * t + 1];
    const int r0 = rslot[2 * t], r1 = rslot[2 * t + 1];
    const float4 a = ((const float4*)(y + (long long)r0 * DIM))[d4];
    const float4 b = ((const float4*)(y + (long long)r1 * DIM))[d4];
    float4 r;
    r.x = w0 * a.x + w1 * b.x;
    r.y = w0 * a.y + w1 * b.y;
    r.z = w0 * a.z + w1 * b.z;
    r.w = w0 * a.w + w1 * b.w;
    ((float4*)out)[i] = r;
}

// ---------------- host ----------------
extern "C" void kernel_launch(void* const* d_in, const int* in_sizes, int n_in,
                              void* d_out, int out_size)
{
    const float* x   = (const float*)d_in[0];
    const float* rw1 = (const float*)d_in[1];
    const float* rw2 = (const float*)d_in[2];
    const float* W1  = (const float*)d_in[3];
    const float* W2  = (const float*)d_in[4];
    float* out = (float*)d_out;

    void *xp, *hp, *yp, *w1t, *w2t, *rpart, *hidp, *rwp, *rslotp, *cntp, *offp;
    cudaGetSymbolAddress(&xp, g_xp);
    cudaGetSymbolAddress(&hp, g_h);
    cudaGetSymbolAddress(&yp, g_y);
    cudaGetSymbolAddress(&w1t, g_w1t);
    cudaGetSymbolAddress(&w2t, g_w2t);
    cudaGetSymbolAddress(&rpart, g_rpart);
    cudaGetSymbolAddress(&hidp, g_hidden);
    cudaGetSymbolAddress(&rwp, g_rw);
    cudaGetSymbolAddress(&rslotp, g_rslot);
    cudaGetSymbolAddress(&cntp, g_cnt);
    cudaGetSymbolAddress(&offp, g_off);

    const int SMEM_H = HSTAGES * SBYT_H;   // 81920
    const int SMEM_R = RSTAGES * SBYT;     // 107520
    cudaFuncSetAttribute(hgemm<true>,
                         cudaFuncAttributeMaxDynamicSharedMemorySize, SMEM_H);
    cudaFuncSetAttribute(hgemm<false>,
                         cudaFuncAttributeMaxDynamicSharedMemorySize, SMEM_H);
    cudaFuncSetAttribute(router_mma,
                         cudaFuncAttributeMaxDynamicSharedMemorySize, SMEM_R);

    // side stream for weight transpose/convert (fork/join via events)
    cudaStream_t s1;
    cudaStreamCreate(&s1);
    cudaEvent_t e0, e1;
    cudaEventCreateWithFlags(&e0, cudaEventDisableTiming);
    cudaEventCreateWithFlags(&e1, cudaEventDisableTiming);

    // 1. zero per-expert counters (main stream)
    zero_cnt_kernel<<<1, 32>>>();
    cudaEventRecord(e0, 0);
    cudaStreamWaitEvent(s1, e0, 0);

    // 2. transpose + half-convert weights on side stream
    //    W1 [e][K=1024][N=2048] -> w1t [e][n][k]
    transpose_half_kernel<<<dim3(FF / 32, DIM / 32, NEXP), dim3(32, 8), 0, s1>>>(
        W1, (__half*)w1t, DIM, FF);
    //    W2 [e][K=2048][N=1024] -> w2t [e][n][k]
    transpose_half_kernel<<<dim3(DIM / 32, FF / 32, NEXP), dim3(32, 8), 0, s1>>>(
        W2, (__half*)w2t, FF, DIM);
    cudaEventRecord(e1, s1);

    // 3. router hidden: 3xtf32 K-split MMA + reduce/silu
    router_mma<<<dim3(KSPLIT, T_TOKENS / 128), 256, SMEM_R>>>(x, rw1, (float*)rpart);
    reduce_silu_kernel<<<(T_TOKENS * RH / 4 + 255) / 256, 256>>>(
        (const float*)rpart, (float*)hidp);

    // 4. router logits + softmax + top-2
    router_topk_kernel<<<T_TOKENS / 8, 256>>>((const float*)hidp, rw2);

    // 5. offsets + gather into expert-contiguous half buffer
    offsets_kernel<<<1, 32>>>();
    dispatch_kernel<<<NSLOTS, 256>>>(x);

    // join: transposed weights ready before grouped GEMMs
    cudaStreamWaitEvent(0, e1, 0);

    // 6. grouped GEMM1: h = silu(x_perm @ W1[e])   [N=FF, K=DIM]
    hgemm<true><<<dim3(FF / 128, T_TOKENS / 128, NEXP), 256, SMEM_H>>>(
        (const __half*)xp, (const __half*)w1t, (__half*)hp, (float*)0,
        FF, DIM, (const int*)cntp, (const int*)offp);

    // 7. grouped GEMM2: y = h @ W2[e]              [N=DIM, K=FF]
    hgemm<false><<<dim3(DIM / 128, T_TOKENS / 128, NEXP), 256, SMEM_H>>>(
        (const __half*)hp, (const __half*)w2t, (__half*)0, (float*)yp,
        DIM, FF, (const int*)cntp, (const int*)offp);

    // 8. weighted combine
    combine_kernel<<<(T_TOKENS * (DIM / 4) + 255) / 256, 256>>>(
        (const float*)yp, (const float*)rwp, (const int*)rslotp, out);
}

// round 10
// speedup vs baseline: 4.8505x; 1.0190x over previous
#include <cuda_runtime.h>
#include <cuda_fp16.h>
#include <cstdint>

// ---------------- problem dims ----------------
#define T_TOKENS 8192
#define DIM      1024
#define FF       2048
#define NEXP     8
#define RH       128
#define NSLOTS   (T_TOKENS * 2)
#define KSPLIT   4

// ---------------- device scratch ----------------
__device__ __half g_xh[(long long)T_TOKENS * DIM];          // x in half (unpermuted)
__device__ __half g_h[(long long)NSLOTS * FF];              // expert hidden (perm order)
__device__ __half g_w1t[(long long)NEXP * FF * DIM];        // W1^T [e][f][d] half
__device__ __half g_w2t[(long long)NEXP * DIM * FF];        // W2^T [e][d][f] half
__device__ float  g_rpart[(long long)KSPLIT * T_TOKENS * RH];
__device__ float  g_hidden[T_TOKENS * RH];
__device__ int    g_tok[NEXP * T_TOKENS];
__device__ int    g_slot[NEXP * T_TOKENS];
__device__ int    g_cnt[NEXP];
__device__ int    g_off[NEXP];
__device__ int    g_ptok[NSLOTS];                           // perm row -> token
__device__ float  g_pw[NSLOTS];                             // perm row -> routing weight
__device__ float  g_rw[NSLOTS];

// ---------------- helpers ----------------
__device__ __forceinline__ uint32_t cvta_s(const void* p) {
    uint32_t a;
    asm("{ .reg .u64 t; cvta.to.shared.u64 t, %1; cvt.u32.u64 %0, t; }" : "=r"(a) : "l"(p));
    return a;
}
__device__ __forceinline__ void cp16(uint32_t s, const void* g) {
    asm volatile("cp.async.cg.shared.global [%0], [%1], 16;" :: "r"(s), "l"(g));
}
__device__ __forceinline__ uint32_t tf32r(float f) {
    uint32_t u;
    asm("cvt.rna.tf32.f32 %0, %1;" : "=r"(u) : "f"(f));
    return u;
}
__device__ __forceinline__ void tf32split(float v, uint32_t& hi, uint32_t& lo) {
    hi = tf32r(v);
    lo = tf32r(v - __uint_as_float(hi));
}
__device__ __forceinline__ float silu_f(float v) { return v / (1.0f + __expf(-v)); }

__device__ __forceinline__ void mma1688(float* c, const uint32_t* a, const uint32_t* b) {
    asm volatile(
        "mma.sync.aligned.m16n8k8.row.col.f32.tf32.tf32.f32 "
        "{%0,%1,%2,%3}, {%4,%5,%6,%7}, {%8,%9}, {%0,%1,%2,%3};"
        : "+f"(c[0]), "+f"(c[1]), "+f"(c[2]), "+f"(c[3])
        : "r"(a[0]), "r"(a[1]), "r"(a[2]), "r"(a[3]), "r"(b[0]), "r"(b[1]));
}
__device__ __forceinline__ void mma16816(float* c, const uint32_t* a, const uint32_t* b) {
    asm volatile(
        "mma.sync.aligned.m16n8k16.row.col.f32.f16.f16.f32 "
        "{%0,%1,%2,%3}, {%4,%5,%6,%7}, {%8,%9}, {%0,%1,%2,%3};"
        : "+f"(c[0]), "+f"(c[1]), "+f"(c[2]), "+f"(c[3])
        : "r"(a[0]), "r"(a[1]), "r"(a[2]), "r"(a[3]), "r"(b[0]), "r"(b[1]));
}

// ================ fp16 grouped GEMM (m16n8k16) ================
// MODE 0: A rows gathered via g_ptok from g_xh; silu -> half out (perm rows).
// MODE 1: A rows direct (perm order); epilogue scales by g_pw and atomicAdds
//         into out[token]. Each out element gets exactly 2 contributions ->
//         commutative fp32 add -> bit-deterministic.
#define HSTAGES 4
#define ASTR_H  40                  // halves per A row (32 + 8 pad)
#define A_HALFS (128 * ASTR_H)      // 5120
#define B_HALFS (128 * ASTR_H)      // 5120
#define SFH     (A_HALFS + B_HALFS) // 10240 halves / stage
#define SBYT_H  (SFH * 2)           // 20480 bytes / stage

template <int MODE>
__global__ __launch_bounds__(256, 2)
void hgemm(const __half* __restrict__ A, const __half* __restrict__ Bt,
           __half* __restrict__ Ch, float* __restrict__ Cf,
           int N, int K,
           const int* __restrict__ cnt, const int* __restrict__ off,
           const int* __restrict__ ptok, const float* __restrict__ pw)
{
    extern __shared__ __half smh[];
    const int e = blockIdx.z;
    const int c = cnt[e], o = off[e];
    if ((int)blockIdx.y * 128 >= c) return;
    const int row0 = o + blockIdx.y * 128;
    const int mend = o + c;
    const int n0 = blockIdx.x * 128;
    const __half* Bp = Bt + (long long)e * N * K;

    const int tid = threadIdx.x;
    const uint32_t sbase = cvta_s(smh);

    // loaders: 2 x 16B for A, 2 x 16B for B per thread
    const __half* aSrc[2]; uint32_t aDst[2];
    const __half* bSrc[2]; uint32_t bDst[2];
#pragma unroll
    for (int i = 0; i < 2; i++) {
        const int idx = tid + i * 256;          // 0..511
        const int ar = idx >> 2, ac = idx & 3;  // row 0..127, 16B chunk 0..3
        int prow = row0 + ar;
        if (prow > mend - 1) prow = mend - 1;
        const long long arow = (MODE == 0) ? (long long)ptok[prow] : (long long)prow;
        aSrc[i] = A + arow * K + ac * 8;
        aDst[i] = sbase + (uint32_t)(ar * 80 + ac * 16);
        const int br = idx >> 2, bc = idx & 3;
        bSrc[i] = Bp + (long long)(n0 + br) * K + bc * 8;
        bDst[i] = sbase + (uint32_t)(A_HALFS * 2 + br * 80 + bc * 16);
    }

    const int nk = K / 32;
    // prologue: stages 0..2
#pragma unroll
    for (int s = 0; s < 3; s++) {
#pragma unroll
        for (int i = 0; i < 2; i++) {
            cp16(aDst[i] + s * SBYT_H, aSrc[i] + s * 32);
            cp16(bDst[i] + s * SBYT_H, bSrc[i] + s * 32);
        }
        asm volatile("cp.async.commit_group;" ::: "memory");
    }

    const int wid = tid >> 5, lane = tid & 31;
    const int wm = (wid & 3) * 32, wn = (wid >> 2) * 64;
    const int l4 = lane >> 2, lq = lane & 3;

    float acc[2][8][4];
#pragma unroll
    for (int mt = 0; mt < 2; mt++)
#pragma unroll
        for (int nt = 0; nt < 8; nt++)
#pragma unroll
            for (int q = 0; q < 4; q++) acc[mt][nt][q] = 0.0f;

    for (int kt = 0; kt < nk; kt++) {
        asm volatile("cp.async.wait_group 2;" ::: "memory");
        __syncthreads();
        if (kt + 3 < nk) {
            const int s = (kt + 3) & 3;
#pragma unroll
            for (int i = 0; i < 2; i++) {
                cp16(aDst[i] + s * SBYT_H, aSrc[i] + (kt + 3) * 32);
                cp16(bDst[i] + s * SBYT_H, bSrc[i] + (kt + 3) * 32);
            }
        }
        asm volatile("cp.async.commit_group;" ::: "memory");

        const __half* st = smh + (kt & 3) * SFH;
#pragma unroll
        for (int ks = 0; ks < 2; ks++) {
            const int kk = ks * 16;
            uint32_t a[2][4], b[8][2];
#pragma unroll
            for (int mt = 0; mt < 2; mt++) {
                const __half* ap = st + (wm + mt * 16 + l4) * ASTR_H + kk + 2 * lq;
                a[mt][0] = *(const uint32_t*)(ap);
                a[mt][1] = *(const uint32_t*)(ap + 8 * ASTR_H);
                a[mt][2] = *(const uint32_t*)(ap + 8);
                a[mt][3] = *(const uint32_t*)(ap + 8 * ASTR_H + 8);
            }
#pragma unroll
            for (int nt = 0; nt < 8; nt++) {
                const __half* bp = st + A_HALFS + (wn + nt * 8 + l4) * ASTR_H + kk + 2 * lq;
                b[nt][0] = *(const uint32_t*)(bp);
                b[nt][1] = *(const uint32_t*)(bp + 8);
            }
#pragma unroll
            for (int mt = 0; mt < 2; mt++)
#pragma unroll
                for (int nt = 0; nt < 8; nt++)
                    mma16816(acc[mt][nt], a[mt], b[nt]);
        }
    }

    // epilogue
#pragma unroll
    for (int mt = 0; mt < 2; mt++) {
#pragma unroll
        for (int hr = 0; hr < 2; hr++) {
            const int row = row0 + wm + mt * 16 + l4 + hr * 8;
            if (row < mend) {
                if (MODE == 0) {
                    __half* cp0 = Ch + (long long)row * N + n0 + wn + lq * 2;
#pragma unroll
                    for (int nt = 0; nt < 8; nt++) {
                        const float v0 = silu_f(acc[mt][nt][hr * 2 + 0]);
                        const float v1 = silu_f(acc[mt][nt][hr * 2 + 1]);
                        *(__half2*)(cp0 + nt * 8) = __floats2half2_rn(v0, v1);
                    }
                } else {
                    const int t = ptok[row];
                    const float w = pw[row];
                    float* cp0 = Cf + (long long)t * N + n0 + wn + lq * 2;
#pragma unroll
                    for (int nt = 0; nt < 8; nt++) {
                        atomicAdd(cp0 + nt * 8 + 0, w * acc[mt][nt][hr * 2 + 0]);
                        atomicAdd(cp0 + nt * 8 + 1, w * acc[mt][nt][hr * 2 + 1]);
                    }
                }
            }
        }
    }
}

// ================ router hidden: 3xtf32 MMA with K-split ================
#define RSTAGES 3
#define ASTR 36
#define BSTR 136
#define AFL  (128 * ASTR)
#define BFL  (32 * BSTR)
#define SF   (AFL + BFL)
#define SBYT (SF * 4)

__global__ __launch_bounds__(256)
void router_mma(const float* __restrict__ x, const float* __restrict__ rw1,
                float* __restrict__ part)
{
    extern __shared__ float sm[];
    const int kz = blockIdx.x;
    const int row0 = blockIdx.y * 128;
    const int kbase = kz * (DIM / KSPLIT);

    const int tid = threadIdx.x;
    const uint32_t sbase = cvta_s(sm);

    const float* aSrc[4]; uint32_t aDst[4];
    const float* bSrc[4]; uint32_t bDst[4];
#pragma unroll
    for (int i = 0; i < 4; i++) {
        const int cidx = tid + i * 256;
        const int ar = cidx >> 3, ak = (cidx & 7) * 4;
        aSrc[i] = x + (long long)(row0 + ar) * DIM + kbase + ak;
        aDst[i] = sbase + (uint32_t)(ar * ASTR + ak) * 4u;
        const int bk = cidx >> 5, bn = (cidx & 31) * 4;
        bSrc[i] = rw1 + (long long)(kbase + bk) * RH + bn;
        bDst[i] = sbase + (uint32_t)(AFL + bk * BSTR + bn) * 4u;
    }

    const int nk = (DIM / KSPLIT) / 32;
#pragma unroll
    for (int s = 0; s < 2; s++) {
#pragma unroll
        for (int i = 0; i < 4; i++) {
            cp16(aDst[i] + s * SBYT, aSrc[i] + s * 32);
            cp16(bDst[i] + s * SBYT, bSrc[i] + (long long)s * 32 * RH);
        }
        asm volatile("cp.async.commit_group;" ::: "memory");
    }

    const int wid = tid >> 5, lane = tid & 31;
    const int wm = (wid & 3) * 32, wn = (wid >> 2) * 64;
    const int l4 = lane >> 2, lq = lane & 3;

    float acc[2][8][4];
#pragma unroll
    for (int mt = 0; mt < 2; mt++)
#pragma unroll
        for (int nt = 0; nt < 8; nt++)
#pragma unroll
            for (int q = 0; q < 4; q++) acc[mt][nt][q] = 0.0f;

    int rstage = 0, pstage = 2;
    for (int kt = 0; kt < nk; kt++) {
        asm volatile("cp.async.wait_group 1;" ::: "memory");
        __syncthreads();
        if (kt + 2 < nk) {
#pragma unroll
            for (int i = 0; i < 4; i++) {
                cp16(aDst[i] + pstage * SBYT, aSrc[i] + (kt + 2) * 32);
                cp16(bDst[i] + pstage * SBYT, bSrc[i] + (long long)(kt + 2) * 32 * RH);
            }
        }
        asm volatile("cp.async.commit_group;" ::: "memory");

        const float* st = sm + rstage * SF;
#pragma unroll
        for (int ks = 0; ks < 4; ks++) {
            const int kk = ks * 8;
            uint32_t ah[2][4], al[2][4], bh[8][2], bl[8][2];
#pragma unroll
            for (int mt = 0; mt < 2; mt++) {
                const float* ap = st + (wm + mt * 16 + l4) * ASTR + kk + lq;
                tf32split(ap[0],            ah[mt][0], al[mt][0]);
                tf32split(ap[8 * ASTR],     ah[mt][1], al[mt][1]);
                tf32split(ap[4],            ah[mt][2], al[mt][2]);
                tf32split(ap[8 * ASTR + 4], ah[mt][3], al[mt][3]);
            }
#pragma unroll
            for (int nt = 0; nt < 8; nt++) {
                const float* bp = st + AFL + (kk + lq) * BSTR + wn + nt * 8 + l4;
                tf32split(bp[0],        bh[nt][0], bl[nt][0]);
                tf32split(bp[4 * BSTR], bh[nt][1], bl[nt][1]);
            }
#pragma unroll
            for (int mt = 0; mt < 2; mt++)
#pragma unroll
                for (int nt = 0; nt < 8; nt++) {
                    mma1688(acc[mt][nt], ah[mt], bh[nt]);
                    mma1688(acc[mt][nt], ah[mt], bl[nt]);
                    mma1688(acc[mt][nt], al[mt], bh[nt]);
                }
        }
        if (++rstage == RSTAGES) rstage = 0;
        if (++pstage == RSTAGES) pstage = 0;
    }

    float* base = part + (long long)kz * T_TOKENS * RH;
#pragma unroll
    for (int mt = 0; mt < 2; mt++) {
#pragma unroll
        for (int hr = 0; hr < 2; hr++) {
            const int row = row0 + wm + mt * 16 + l4 + hr * 8;
            float* cp0 = base + (long long)row * RH + wn + lq * 2;
#pragma unroll
            for (int nt = 0; nt < 8; nt++) {
                float2 v;
                v.x = acc[mt][nt][hr * 2 + 0];
                v.y = acc[mt][nt][hr * 2 + 1];
                *(float2*)(cp0 + nt * 8) = v;
            }
        }
    }
}

__global__ void reduce_silu_kernel(const float* __restrict__ part,
                                   float* __restrict__ hid)
{
    const int i = blockIdx.x * blockDim.x + threadIdx.x;
    const int total = T_TOKENS * RH / 4;
    if (i >= total) return;
    const long long stride = (long long)T_TOKENS * RH / 4;
    float4 s = ((const float4*)part)[i];
#pragma unroll
    for (int kz = 1; kz < KSPLIT; kz++) {
        const float4 v = ((const float4*)part)[i + kz * stride];
        s.x += v.x; s.y += v.y; s.z += v.z; s.w += v.w;
    }
    s.x = silu_f(s.x); s.y = silu_f(s.y); s.z = silu_f(s.z); s.w = silu_f(s.w);
    ((float4*)hid)[i] = s;
}

// ---------------- conversions ----------------
// src [e][R][C] fp32 -> dst [e][C][R] half
__global__ void transpose_half_kernel(const float* __restrict__ src,
                                      __half* __restrict__ dst, int R, int C)
{
    __shared__ float tile[32][33];
    const int e = blockIdx.z;
    const float* s = src + (long long)e * R * C;
    __half* d = dst + (long long)e * R * C;
    const int c0 = blockIdx.x * 32, r0 = blockIdx.y * 32;
    const int tx = threadIdx.x, ty = threadIdx.y;
#pragma unroll
    for (int i = 0; i < 32; i += 8)
        tile[ty + i][tx] = s[(long long)(r0 + ty + i) * C + c0 + tx];
    __syncthreads();
#pragma unroll
    for (int i = 0; i < 32; i += 8)
        d[(long long)(c0 + ty + i) * R + r0 + tx] = __float2half_rn(tile[tx][ty + i]);
}

__global__ void x2half_kernel(const float* __restrict__ x, __half* __restrict__ xh)
{
    const int i = blockIdx.x * blockDim.x + threadIdx.x;
    if (i >= T_TOKENS * DIM / 4) return;
    const float4 v = ((const float4*)x)[i];
    const __half2 h0 = __floats2half2_rn(v.x, v.y);
    const __half2 h1 = __floats2half2_rn(v.z, v.w);
    uint2 u;
    u.x = *(const uint32_t*)&h0;
    u.y = *(const uint32_t*)&h1;
    ((uint2*)xh)[i] = u;
}

__global__ void zero_out_kernel(float* __restrict__ out)
{
    const int i = blockIdx.x * blockDim.x + threadIdx.x;
    if (i < T_TOKENS * DIM / 4)
        ((float4*)out)[i] = make_float4(0.f, 0.f, 0.f, 0.f);
}

// ---------------- routing ----------------
__global__ void router_topk_kernel(const float* __restrict__ hidden,
                                   const float* __restrict__ w2)
{
    const int warp = (blockIdx.x * blockDim.x + threadIdx.x) >> 5;
    const int lane = threadIdx.x & 31;
    if (warp >= T_TOKENS) return;
    const float* h = hidden + warp * RH;
    float acc[NEXP];
#pragma unroll
    for (int e = 0; e < NEXP; e++) acc[e] = 0.0f;
    for (int j = lane; j < RH; j += 32) {
        const float hv = h[j];
#pragma unroll
        for (int e = 0; e < NEXP; e++) acc[e] += hv * w2[j * NEXP + e];
    }
#pragma unroll
    for (int off = 16; off > 0; off >>= 1)
#pragma unroll
        for (int e = 0; e < NEXP; e++)
            acc[e] += __shfl_xor_sync(0xffffffffu, acc[e], off);
    if (lane == 0) {
        float mx = acc[0];
#pragma unroll
        for (int e = 1; e < NEXP; e++) mx = fmaxf(mx, acc[e]);
        float p[NEXP];
#pragma unroll
        for (int e = 0; e < NEXP; e++) p[e] = __expf(acc[e] - mx);
        int i0 = 0;
#pragma unroll
        for (int e = 1; e < NEXP; e++) if (p[e] > p[i0]) i0 = e;
        int i1 = (i0 == 0) ? 1 : 0;
#pragma unroll
        for (int e = 0; e < NEXP; e++) if (e != i0 && p[e] > p[i1]) i1 = e;
        const float s = p[i0] + p[i1];
        const int t = warp;
        int pos0 = atomicAdd(&g_cnt[i0], 1);
        g_tok[i0 * T_TOKENS + pos0]  = t;
        g_slot[i0 * T_TOKENS + pos0] = 2 * t;
        g_rw[2 * t] = p[i0] / s;
        int pos1 = atomicAdd(&g_cnt[i1], 1);
        g_tok[i1 * T_TOKENS + pos1]  = t;
        g_slot[i1 * T_TOKENS + pos1] = 2 * t + 1;
        g_rw[2 * t + 1] = p[i1] / s;
    }
}

__global__ void zero_cnt_kernel() { if (threadIdx.x < NEXP) g_cnt[threadIdx.x] = 0; }

__global__ void offsets_kernel() {
    if (threadIdx.x == 0) {
        int s = 0;
        for (int e = 0; e < NEXP; e++) { g_off[e] = s; s += g_cnt[e]; }
    }
}

// per-perm-row metadata: token index + routing weight
__global__ void dispatch_meta_kernel()
{
    const int l = blockIdx.x * blockDim.x + threadIdx.x;
    if (l >= NSLOTS) return;
    int e = 0;
#pragma unroll
    for (int k = 1; k < NEXP; k++) if (l >= g_off[k]) e = k;
    const int p = l - g_off[e];
    const int t = g_tok[e * T_TOKENS + p];
    g_ptok[l] = t;
    g_pw[l] = g_rw[g_slot[e * T_TOKENS + p]];
}

// ---------------- host ----------------
extern "C" void kernel_launch(void* const* d_in, const int* in_sizes, int n_in,
                              void* d_out, int out_size)
{
    const float* x   = (const float*)d_in[0];
    const float* rw1 = (const float*)d_in[1];
    const float* rw2 = (const float*)d_in[2];
    const float* W1  = (const float*)d_in[3];
    const float* W2  = (const float*)d_in[4];
    float* out = (float*)d_out;

    void *xh, *hp, *w1t, *w2t, *rpart, *hidp, *cntp, *offp, *ptokp, *pwp;
    cudaGetSymbolAddress(&xh, g_xh);
    cudaGetSymbolAddress(&hp, g_h);
    cudaGetSymbolAddress(&w1t, g_w1t);
    cudaGetSymbolAddress(&w2t, g_w2t);
    cudaGetSymbolAddress(&rpart, g_rpart);
    cudaGetSymbolAddress(&hidp, g_hidden);
    cudaGetSymbolAddress(&cntp, g_cnt);
    cudaGetSymbolAddress(&offp, g_off);
    cudaGetSymbolAddress(&ptokp, g_ptok);
    cudaGetSymbolAddress(&pwp, g_pw);

    const int SMEM_H = HSTAGES * SBYT_H;   // 81920
    const int SMEM_R = RSTAGES * SBYT;     // 107520
    cudaFuncSetAttribute(hgemm<0>,
                         cudaFuncAttributeMaxDynamicSharedMemorySize, SMEM_H);
    cudaFuncSetAttribute(hgemm<1>,
                         cudaFuncAttributeMaxDynamicSharedMemorySize, SMEM_H);
    cudaFuncSetAttribute(router_mma,
                         cudaFuncAttributeMaxDynamicSharedMemorySize, SMEM_R);

    // side stream (fork/join via events; capture-legal)
    cudaStream_t s1;
    cudaStreamCreate(&s1);
    cudaEvent_t e0, e1;
    cudaEventCreateWithFlags(&e0, cudaEventDisableTiming);
    cudaEventCreateWithFlags(&e1, cudaEventDisableTiming);

    // 1. zero counters + output accumulator (main stream)
    zero_cnt_kernel<<<1, 32>>>();
    zero_out_kernel<<<(T_TOKENS * DIM / 4 + 255) / 256, 256>>>(out);
    cudaEventRecord(e0, 0);
    cudaStreamWaitEvent(s1, e0, 0);

    // 2. side stream: weight transposes + x->half (overlap router chain)
    transpose_half_kernel<<<dim3(FF / 32, DIM / 32, NEXP), dim3(32, 8), 0, s1>>>(
        W1, (__half*)w1t, DIM, FF);
    transpose_half_kernel<<<dim3(DIM / 32, FF / 32, NEXP), dim3(32, 8), 0, s1>>>(
        W2, (__half*)w2t, FF, DIM);
    x2half_kernel<<<(T_TOKENS * DIM / 4 + 255) / 256, 256, 0, s1>>>(x, (__half*)xh);
    cudaEventRecord(e1, s1);

    // 3. router hidden: 3xtf32 K-split MMA + reduce/silu
    router_mma<<<dim3(KSPLIT, T_TOKENS / 128), 256, SMEM_R>>>(x, rw1, (float*)rpart);
    reduce_silu_kernel<<<(T_TOKENS * RH / 4 + 255) / 256, 256>>>(
        (const float*)rpart, (float*)hidp);

    // 4. router logits + softmax + top-2
    router_topk_kernel<<<T_TOKENS / 8, 256>>>((const float*)hidp, rw2);

    // 5. offsets + perm-row metadata
    offsets_kernel<<<1, 32>>>();
    dispatch_meta_kernel<<<(NSLOTS + 255) / 256, 256>>>();

    // join: side-stream conversions done
    cudaStreamWaitEvent(0, e1, 0);

    // 6. grouped GEMM1 (gather-A): h = silu(x[tok] @ W1[e])
    hgemm<0><<<dim3(FF / 128, T_TOKENS / 128, NEXP), 256, SMEM_H>>>(
        (const __half*)xh, (const __half*)w1t, (__half*)hp, (float*)0,
        FF, DIM, (const int*)cntp, (const int*)offp,
        (const int*)ptokp, (const float*)pwp);

    // 7. grouped GEMM2 (weighted atomic scatter): out[t] += w * (h @ W2[e])
    hgemm<1><<<dim3(DIM / 128, T_TOKENS / 128, NEXP), 256, SMEM_H>>>(
        (const __half*)hp, (const __half*)w2t, (__half*)0, out,
        DIM, FF, (const int*)cntp, (const int*)offp,
        (const int*)ptokp, (const float*)pwp);
}

// round 11
// speedup vs baseline: 5.0669x; 1.0446x over previous
#include <cuda_runtime.h>
#include <cuda_fp16.h>
#include <cstdint>

// ---------------- problem dims ----------------
#define T_TOKENS 8192
#define DIM      1024
#define FF       2048
#define NEXP     8
#define RH       128
#define NSLOTS   (T_TOKENS * 2)
#define KSPLIT   4

// ---------------- device scratch ----------------
__device__ __half g_xh[(long long)T_TOKENS * DIM];          // x in half (unpermuted)
__device__ __half g_h[(long long)NSLOTS * FF];              // expert hidden (perm order)
__device__ __half g_w1t[(long long)NEXP * FF * DIM];        // W1^T [e][f][d] half
__device__ __half g_w2t[(long long)NEXP * DIM * FF];        // W2^T [e][d][f] half
__device__ float  g_rpart[(long long)KSPLIT * T_TOKENS * RH];
__device__ int    g_tok[NEXP * T_TOKENS];
__device__ int    g_slot[NEXP * T_TOKENS];
__device__ int    g_cnt[NEXP];
__device__ int    g_off[NEXP];
__device__ int    g_ptok[NSLOTS];                           // perm row -> token
__device__ float  g_pw[NSLOTS];                             // perm row -> routing weight
__device__ float  g_rw[NSLOTS];

// ---------------- helpers ----------------
__device__ __forceinline__ uint32_t cvta_s(const void* p) {
    uint32_t a;
    asm("{ .reg .u64 t; cvta.to.shared.u64 t, %1; cvt.u32.u64 %0, t; }" : "=r"(a) : "l"(p));
    return a;
}
__device__ __forceinline__ void cp16(uint32_t s, const void* g) {
    asm volatile("cp.async.cg.shared.global [%0], [%1], 16;" :: "r"(s), "l"(g));
}
__device__ __forceinline__ float silu_f(float v) { return v / (1.0f + __expf(-v)); }

__device__ __forceinline__ void mma16816(float* c, const uint32_t* a, const uint32_t* b) {
    asm volatile(
        "mma.sync.aligned.m16n8k16.row.col.f32.f16.f16.f32 "
        "{%0,%1,%2,%3}, {%4,%5,%6,%7}, {%8,%9}, {%0,%1,%2,%3};"
        : "+f"(c[0]), "+f"(c[1]), "+f"(c[2]), "+f"(c[3])
        : "r"(a[0]), "r"(a[1]), "r"(a[2]), "r"(a[3]), "r"(b[0]), "r"(b[1]));
}

// split a pair of fp32 into packed half2 hi + half2 lo (fp16x3 scheme)
__device__ __forceinline__ void splitpair(float x, float y, uint32_t& hi, uint32_t& lo) {
    const __half2 h = __floats2half2_rn(x, y);
    const float2 hf = __half22float2(h);
    const __half2 l = __floats2half2_rn(x - hf.x, y - hf.y);
    hi = *(const uint32_t*)&h;
    lo = *(const uint32_t*)&l;
}

// ================ fp16 grouped GEMM (m16n8k16) ================
// MODE 0: A rows gathered via ptok from g_xh; silu -> half out (perm rows).
// MODE 1: A rows direct (perm order); epilogue scales by pw and atomicAdds
//         into out[token]. Exactly 2 contributions per element -> commutative
//         fp32 add -> bit-deterministic.
#define HSTAGES 4
#define ASTR_H  40                  // halves per A row (32 + 8 pad)
#define A_HALFS (128 * ASTR_H)      // 5120
#define B_HALFS (128 * ASTR_H)      // 5120
#define SFH     (A_HALFS + B_HALFS) // 10240 halves / stage
#define SBYT_H  (SFH * 2)           // 20480 bytes / stage

template <int MODE>
__global__ __launch_bounds__(256, 2)
void hgemm(const __half* __restrict__ A, const __half* __restrict__ Bt,
           __half* __restrict__ Ch, float* __restrict__ Cf,
           int N, int K,
           const int* __restrict__ cnt, const int* __restrict__ off,
           const int* __restrict__ ptok, const float* __restrict__ pw)
{
    extern __shared__ __half smh[];
    const int e = blockIdx.z;
    const int c = cnt[e], o = off[e];
    if ((int)blockIdx.y * 128 >= c) return;
    const int row0 = o + blockIdx.y * 128;
    const int mend = o + c;
    const int n0 = blockIdx.x * 128;
    const __half* Bp = Bt + (long long)e * N * K;

    const int tid = threadIdx.x;
    const uint32_t sbase = cvta_s(smh);

    const __half* aSrc[2]; uint32_t aDst[2];
    const __half* bSrc[2]; uint32_t bDst[2];
#pragma unroll
    for (int i = 0; i < 2; i++) {
        const int idx = tid + i * 256;
        const int ar = idx >> 2, ac = idx & 3;
        int prow = row0 + ar;
        if (prow > mend - 1) prow = mend - 1;
        const long long arow = (MODE == 0) ? (long long)ptok[prow] : (long long)prow;
        aSrc[i] = A + arow * K + ac * 8;
        aDst[i] = sbase + (uint32_t)(ar * 80 + ac * 16);
        const int br = idx >> 2, bc = idx & 3;
        bSrc[i] = Bp + (long long)(n0 + br) * K + bc * 8;
        bDst[i] = sbase + (uint32_t)(A_HALFS * 2 + br * 80 + bc * 16);
    }

    const int nk = K / 32;
#pragma unroll
    for (int s = 0; s < 3; s++) {
#pragma unroll
        for (int i = 0; i < 2; i++) {
            cp16(aDst[i] + s * SBYT_H, aSrc[i] + s * 32);
            cp16(bDst[i] + s * SBYT_H, bSrc[i] + s * 32);
        }
        asm volatile("cp.async.commit_group;" ::: "memory");
    }

    const int wid = tid >> 5, lane = tid & 31;
    const int wm = (wid & 3) * 32, wn = (wid >> 2) * 64;
    const int l4 = lane >> 2, lq = lane & 3;

    float acc[2][8][4];
#pragma unroll
    for (int mt = 0; mt < 2; mt++)
#pragma unroll
        for (int nt = 0; nt < 8; nt++)
#pragma unroll
            for (int q = 0; q < 4; q++) acc[mt][nt][q] = 0.0f;

    for (int kt = 0; kt < nk; kt++) {
        asm volatile("cp.async.wait_group 2;" ::: "memory");
        __syncthreads();
        if (kt + 3 < nk) {
            const int s = (kt + 3) & 3;
#pragma unroll
            for (int i = 0; i < 2; i++) {
                cp16(aDst[i] + s * SBYT_H, aSrc[i] + (kt + 3) * 32);
                cp16(bDst[i] + s * SBYT_H, bSrc[i] + (kt + 3) * 32);
            }
        }
        asm volatile("cp.async.commit_group;" ::: "memory");

        const __half* st = smh + (kt & 3) * SFH;
#pragma unroll
        for (int ks = 0; ks < 2; ks++) {
            const int kk = ks * 16;
            uint32_t a[2][4], b[8][2];
#pragma unroll
            for (int mt = 0; mt < 2; mt++) {
                const __half* ap = st + (wm + mt * 16 + l4) * ASTR_H + kk + 2 * lq;
                a[mt][0] = *(const uint32_t*)(ap);
                a[mt][1] = *(const uint32_t*)(ap + 8 * ASTR_H);
                a[mt][2] = *(const uint32_t*)(ap + 8);
                a[mt][3] = *(const uint32_t*)(ap + 8 * ASTR_H + 8);
            }
#pragma unroll
            for (int nt = 0; nt < 8; nt++) {
                const __half* bp = st + A_HALFS + (wn + nt * 8 + l4) * ASTR_H + kk + 2 * lq;
                b[nt][0] = *(const uint32_t*)(bp);
                b[nt][1] = *(const uint32_t*)(bp + 8);
            }
#pragma unroll
            for (int mt = 0; mt < 2; mt++)
#pragma unroll
                for (int nt = 0; nt < 8; nt++)
                    mma16816(acc[mt][nt], a[mt], b[nt]);
        }
    }

    // epilogue
#pragma unroll
    for (int mt = 0; mt < 2; mt++) {
#pragma unroll
        for (int hr = 0; hr < 2; hr++) {
            const int row = row0 + wm + mt * 16 + l4 + hr * 8;
            if (row < mend) {
                if (MODE == 0) {
                    __half* cp0 = Ch + (long long)row * N + n0 + wn + lq * 2;
#pragma unroll
                    for (int nt = 0; nt < 8; nt++) {
                        const float v0 = silu_f(acc[mt][nt][hr * 2 + 0]);
                        const float v1 = silu_f(acc[mt][nt][hr * 2 + 1]);
                        *(__half2*)(cp0 + nt * 8) = __floats2half2_rn(v0, v1);
                    }
                } else {
                    const int t = ptok[row];
                    const float w = pw[row];
                    float* cp0 = Cf + (long long)t * N + n0 + wn + lq * 2;
#pragma unroll
                    for (int nt = 0; nt < 8; nt++) {
                        atomicAdd(cp0 + nt * 8 + 0, w * acc[mt][nt][hr * 2 + 0]);
                        atomicAdd(cp0 + nt * 8 + 1, w * acc[mt][nt][hr * 2 + 1]);
                    }
                }
            }
        }
    }
}

// ================ router hidden: fp16x3 MMA with K-split ================
// part[kz][t][j] = x[t, kz*256:(kz+1)*256] @ rw1[kz*256:..., j]
// fp16x3: a = ah+al, b = bh+bl; acc += ah*bh + ah*bl + al*bh (fp32 accum).
#define RSTAGES 3
#define ASTR 36
#define BSTR 136
#define AFL  (128 * ASTR)
#define BFL  (32 * BSTR)
#define SF   (AFL + BFL)
#define SBYT (SF * 4)

__global__ __launch_bounds__(256)
void router_mma(const float* __restrict__ x, const float* __restrict__ rw1,
                float* __restrict__ part)
{
    extern __shared__ float sm[];
    const int kz = blockIdx.x;
    const int row0 = blockIdx.y * 128;
    const int kbase = kz * (DIM / KSPLIT);

    const int tid = threadIdx.x;
    const uint32_t sbase = cvta_s(sm);

    const float* aSrc[4]; uint32_t aDst[4];
    const float* bSrc[4]; uint32_t bDst[4];
#pragma unroll
    for (int i = 0; i < 4; i++) {
        const int cidx = tid + i * 256;
        const int ar = cidx >> 3, ak = (cidx & 7) * 4;
        aSrc[i] = x + (long long)(row0 + ar) * DIM + kbase + ak;
        aDst[i] = sbase + (uint32_t)(ar * ASTR + ak) * 4u;
        const int bk = cidx >> 5, bn = (cidx & 31) * 4;
        bSrc[i] = rw1 + (long long)(kbase + bk) * RH + bn;
        bDst[i] = sbase + (uint32_t)(AFL + bk * BSTR + bn) * 4u;
    }

    const int nk = (DIM / KSPLIT) / 32;    // 8
#pragma unroll
    for (int s = 0; s < 2; s++) {
#pragma unroll
        for (int i = 0; i < 4; i++) {
            cp16(aDst[i] + s * SBYT, aSrc[i] + s * 32);
            cp16(bDst[i] + s * SBYT, bSrc[i] + (long long)s * 32 * RH);
        }
        asm volatile("cp.async.commit_group;" ::: "memory");
    }

    const int wid = tid >> 5, lane = tid & 31;
    const int wm = (wid & 3) * 32, wn = (wid >> 2) * 64;
    const int l4 = lane >> 2, lq = lane & 3;

    float acc[2][8][4];
#pragma unroll
    for (int mt = 0; mt < 2; mt++)
#pragma unroll
        for (int nt = 0; nt < 8; nt++)
#pragma unroll
            for (int q = 0; q < 4; q++) acc[mt][nt][q] = 0.0f;

    int rstage = 0, pstage = 2;
    for (int kt = 0; kt < nk; kt++) {
        asm volatile("cp.async.wait_group 1;" ::: "memory");
        __syncthreads();
        if (kt + 2 < nk) {
#pragma unroll
            for (int i = 0; i < 4; i++) {
                cp16(aDst[i] + pstage * SBYT, aSrc[i] + (kt + 2) * 32);
                cp16(bDst[i] + pstage * SBYT, bSrc[i] + (long long)(kt + 2) * 32 * RH);
            }
        }
        asm volatile("cp.async.commit_group;" ::: "memory");

        const float* st = sm + rstage * SF;
#pragma unroll
        for (int ks = 0; ks < 2; ks++) {
            const int kk = ks * 16;
            uint32_t ah[2][4], al[2][4], bh[8][2], bl[8][2];
#pragma unroll
            for (int mt = 0; mt < 2; mt++) {
                // fp16 m16n8k16 A frag: (row, k-pair) per reg
                const float* ap = st + (wm + mt * 16 + l4) * ASTR + kk + 2 * lq;
                splitpair(ap[0],              ap[1],              ah[mt][0], al[mt][0]);
                splitpair(ap[8 * ASTR],       ap[8 * ASTR + 1],   ah[mt][1], al[mt][1]);
                splitpair(ap[8],              ap[9],              ah[mt][2], al[mt][2]);
                splitpair(ap[8 * ASTR + 8],   ap[8 * ASTR + 9],   ah[mt][3], al[mt][3]);
            }
#pragma unroll
            for (int nt = 0; nt < 8; nt++) {
                // B frag: n from l4, k-pair from lq; smem B is [k][n] (BSTR)
                const float* bp = st + AFL + (kk + 2 * lq) * BSTR + wn + nt * 8 + l4;
                splitpair(bp[0],        bp[BSTR],     bh[nt][0], bl[nt][0]);
                splitpair(bp[8 * BSTR], bp[9 * BSTR], bh[nt][1], bl[nt][1]);
            }
#pragma unroll
            for (int mt = 0; mt < 2; mt++)
#pragma unroll
                for (int nt = 0; nt < 8; nt++) {
                    mma16816(acc[mt][nt], ah[mt], bh[nt]);
                    mma16816(acc[mt][nt], ah[mt], bl[nt]);
                    mma16816(acc[mt][nt], al[mt], bh[nt]);
                }
        }
        if (++rstage == RSTAGES) rstage = 0;
        if (++pstage == RSTAGES) pstage = 0;
    }

    float* base = part + (long long)kz * T_TOKENS * RH;
#pragma unroll
    for (int mt = 0; mt < 2; mt++) {
#pragma unroll
        for (int hr = 0; hr < 2; hr++) {
            const int row = row0 + wm + mt * 16 + l4 + hr * 8;
            float* cp0 = base + (long long)row * RH + wn + lq * 2;
#pragma unroll
            for (int nt = 0; nt < 8; nt++) {
                float2 v;
                v.x = acc[mt][nt][hr * 2 + 0];
                v.y = acc[mt][nt][hr * 2 + 1];
                *(float2*)(cp0 + nt * 8) = v;
            }
        }
    }
}

// ---------------- fused: KSPLIT-reduce + silu + logits + top-2 ----------------
__global__ void router_topk_kernel(const float* __restrict__ part,
                                   const float* __restrict__ w2)
{
    const int warp = (blockIdx.x * blockDim.x + threadIdx.x) >> 5;
    const int lane = threadIdx.x & 31;
    if (warp >= T_TOKENS) return;
    const long long stride = (long long)T_TOKENS * RH;
    const long long base = (long long)warp * RH;

    float acc[NEXP];
#pragma unroll
    for (int e = 0; e < NEXP; e++) acc[e] = 0.0f;
#pragma unroll
    for (int j4 = 0; j4 < RH / 32; j4++) {
        const int j = j4 * 32 + lane;
        float s = part[base + j];
#pragma unroll
        for (int kz = 1; kz < KSPLIT; kz++) s += part[base + j + kz * stride];
        s = silu_f(s);
#pragma unroll
        for (int e = 0; e < NEXP; e++) acc[e] += s * w2[j * NEXP + e];
    }
#pragma unroll
    for (int off = 16; off > 0; off >>= 1)
#pragma unroll
        for (int e = 0; e < NEXP; e++)
            acc[e] += __shfl_xor_sync(0xffffffffu, acc[e], off);
    if (lane == 0) {
        float mx = acc[0];
#pragma unroll
        for (int e = 1; e < NEXP; e++) mx = fmaxf(mx, acc[e]);
        float p[NEXP];
#pragma unroll
        for (int e = 0; e < NEXP; e++) p[e] = __expf(acc[e] - mx);
        int i0 = 0;
#pragma unroll
        for (int e = 1; e < NEXP; e++) if (p[e] > p[i0]) i0 = e;
        int i1 = (i0 == 0) ? 1 : 0;
#pragma unroll
        for (int e = 0; e < NEXP; e++) if (e != i0 && p[e] > p[i1]) i1 = e;
        const float s = p[i0] + p[i1];
        const int t = warp;
        int pos0 = atomicAdd(&g_cnt[i0], 1);
        g_tok[i0 * T_TOKENS + pos0]  = t;
        g_slot[i0 * T_TOKENS + pos0] = 2 * t;
        g_rw[2 * t] = p[i0] / s;
        int pos1 = atomicAdd(&g_cnt[i1], 1);
        g_tok[i1 * T_TOKENS + pos1]  = t;
        g_slot[i1 * T_TOKENS + pos1] = 2 * t + 1;
        g_rw[2 * t + 1] = p[i1] / s;
    }
}

// ---------------- conversions ----------------
__global__ void transpose_half_kernel(const float* __restrict__ src,
                                      __half* __restrict__ dst, int R, int C)
{
    __shared__ float tile[32][33];
    const int e = blockIdx.z;
    const float* s = src + (long long)e * R * C;
    __half* d = dst + (long long)e * R * C;
    const int c0 = blockIdx.x * 32, r0 = blockIdx.y * 32;
    const int tx = threadIdx.x, ty = threadIdx.y;
#pragma unroll
    for (int i = 0; i < 32; i += 8)
        tile[ty + i][tx] = s[(long long)(r0 + ty + i) * C + c0 + tx];
    __syncthreads();
#pragma unroll
    for (int i = 0; i < 32; i += 8)
        d[(long long)(c0 + ty + i) * R + r0 + tx] = __float2half_rn(tile[tx][ty + i]);
}

__global__ void x2half_kernel(const float* __restrict__ x, __half* __restrict__ xh)
{
    const int i = blockIdx.x * blockDim.x + threadIdx.x;
    if (i >= T_TOKENS * DIM / 4) return;
    const float4 v = ((const float4*)x)[i];
    const __half2 h0 = __floats2half2_rn(v.x, v.y);
    const __half2 h1 = __floats2half2_rn(v.z, v.w);
    uint2 u;
    u.x = *(const uint32_t*)&h0;
    u.y = *(const uint32_t*)&h1;
    ((uint2*)xh)[i] = u;
}

__global__ void zero_out_kernel(float* __restrict__ out)
{
    const int i = blockIdx.x * blockDim.x + threadIdx.x;
    if (i < T_TOKENS * DIM / 4)
        ((float4*)out)[i] = make_float4(0.f, 0.f, 0.f, 0.f);
}

__global__ void zero_cnt_kernel() { if (threadIdx.x < NEXP) g_cnt[threadIdx.x] = 0; }

__global__ void offsets_kernel() {
    if (threadIdx.x == 0) {
        int s = 0;
        for (int e = 0; e < NEXP; e++) { g_off[e] = s; s += g_cnt[e]; }
    }
}

__global__ void dispatch_meta_kernel()
{
    const int l = blockIdx.x * blockDim.x + threadIdx.x;
    if (l >= NSLOTS) return;
    int e = 0;
#pragma unroll
    for (int k = 1; k < NEXP; k++) if (l >= g_off[k]) e = k;
    const int p = l - g_off[e];
    const int t = g_tok[e * T_TOKENS + p];
    g_ptok[l] = t;
    g_pw[l] = g_rw[g_slot[e * T_TOKENS + p]];
}

// ---------------- host ----------------
extern "C" void kernel_launch(void* const* d_in, const int* in_sizes, int n_in,
                              void* d_out, int out_size)
{
    const float* x   = (const float*)d_in[0];
    const float* rw1 = (const float*)d_in[1];
    const float* rw2 = (const float*)d_in[2];
    const float* W1  = (const float*)d_in[3];
    const float* W2  = (const float*)d_in[4];
    float* out = (float*)d_out;

    void *xh, *hp, *w1t, *w2t, *rpart, *cntp, *offp, *ptokp, *pwp;
    cudaGetSymbolAddress(&xh, g_xh);
    cudaGetSymbolAddress(&hp, g_h);
    cudaGetSymbolAddress(&w1t, g_w1t);
    cudaGetSymbolAddress(&w2t, g_w2t);
    cudaGetSymbolAddress(&rpart, g_rpart);
    cudaGetSymbolAddress(&cntp, g_cnt);
    cudaGetSymbolAddress(&offp, g_off);
    cudaGetSymbolAddress(&ptokp, g_ptok);
    cudaGetSymbolAddress(&pwp, g_pw);

    const int SMEM_H = HSTAGES * SBYT_H;   // 81920
    const int SMEM_R = RSTAGES * SBYT;     // 107520
    cudaFuncSetAttribute(hgemm<0>,
                         cudaFuncAttributeMaxDynamicSharedMemorySize, SMEM_H);
    cudaFuncSetAttribute(hgemm<1>,
                         cudaFuncAttributeMaxDynamicSharedMemorySize, SMEM_H);
    cudaFuncSetAttribute(router_mma,
                         cudaFuncAttributeMaxDynamicSharedMemorySize, SMEM_R);

    // side stream (fork/join via events; capture-legal)
    cudaStream_t s1;
    cudaStreamCreate(&s1);
    cudaEvent_t e0, e1;
    cudaEventCreateWithFlags(&e0, cudaEventDisableTiming);
    cudaEventCreateWithFlags(&e1, cudaEventDisableTiming);

    // 1. zero counters (main); fork side stream
    zero_cnt_kernel<<<1, 32>>>();
    cudaEventRecord(e0, 0);
    cudaStreamWaitEvent(s1, e0, 0);

    // 2. side stream: out-zero + weight transposes + x->half (hidden under router)
    zero_out_kernel<<<(T_TOKENS * DIM / 4 + 255) / 256, 256, 0, s1>>>(out);
    transpose_half_kernel<<<dim3(FF / 32, DIM / 32, NEXP), dim3(32, 8), 0, s1>>>(
        W1, (__half*)w1t, DIM, FF);
    transpose_half_kernel<<<dim3(DIM / 32, FF / 32, NEXP), dim3(32, 8), 0, s1>>>(
        W2, (__half*)w2t, FF, DIM);
    x2half_kernel<<<(T_TOKENS * DIM / 4 + 255) / 256, 256, 0, s1>>>(x, (__half*)xh);
    cudaEventRecord(e1, s1);

    // 3. router hidden partials (fp16x3 K-split MMA)
    router_mma<<<dim3(KSPLIT, T_TOKENS / 128), 256, SMEM_R>>>(x, rw1, (float*)rpart);

    // 4. fused reduce+silu+logits+top-2
    router_topk_kernel<<<T_TOKENS / 8, 256>>>((const float*)rpart, rw2);

    // 5. offsets + perm-row metadata
    offsets_kernel<<<1, 32>>>();
    dispatch_meta_kernel<<<(NSLOTS + 255) / 256, 256>>>();

    // join side stream
    cudaStreamWaitEvent(0, e1, 0);

    // 6. grouped GEMM1 (gather-A): h = silu(x[tok] @ W1[e])
    hgemm<0><<<dim3(FF / 128, T_TOKENS / 128, NEXP), 256, SMEM_H>>>(
        (const __half*)xh, (const __half*)w1t, (__half*)hp, (float*)0,
        FF, DIM, (const int*)cntp, (const int*)offp,
        (const int*)ptokp, (const float*)pwp);

    // 7. grouped GEMM2 (weighted atomic scatter): out[t] += w * (h @ W2[e])
    hgemm<1><<<dim3(DIM / 128, T_TOKENS / 128, NEXP), 256, SMEM_H>>>(
        (const __half*)hp, (const __half*)w2t, (__half*)0, out,
        DIM, FF, (const int*)cntp, (const int*)offp,
        (const int*)ptokp, (const float*)pwp);
}

// round 14
// speedup vs baseline: 5.0753x; 1.0017x over previous
#include <cuda_runtime.h>
#include <cuda_fp16.h>
#include <cstdint>

// ---------------- problem dims ----------------
#define T_TOKENS 8192
#define DIM      1024
#define FF       2048
#define NEXP     8
#define RH       128
#define NSLOTS   (T_TOKENS * 2)
#define KSPLIT   4

// ---------------- device scratch ----------------
__device__ __half g_xh[(long long)T_TOKENS * DIM];          // x in half (unpermuted)
__device__ __half g_h[(long long)NSLOTS * FF];              // expert hidden (perm order)
__device__ __half g_w1t[(long long)NEXP * FF * DIM];        // W1^T [e][f][d] half
__device__ __half g_w2t[(long long)NEXP * DIM * FF];        // W2^T [e][d][f] half
__device__ float  g_rpart[(long long)KSPLIT * T_TOKENS * RH];
__device__ int    g_tok[NEXP * T_TOKENS];
__device__ int    g_slot[NEXP * T_TOKENS];
__device__ int    g_cnt[NEXP];
__device__ int    g_off[NEXP];
__device__ int    g_ptok[NSLOTS];                           // perm row -> token
__device__ float  g_pw[NSLOTS];                             // perm row -> routing weight
__device__ float  g_rw[NSLOTS];

// ---------------- helpers ----------------
__device__ __forceinline__ uint32_t cvta_s(const void* p) {
    uint32_t a;
    asm("{ .reg .u64 t; cvta.to.shared.u64 t, %1; cvt.u32.u64 %0, t; }" : "=r"(a) : "l"(p));
    return a;
}
__device__ __forceinline__ void cp16(uint32_t s, const void* g) {
    asm volatile("cp.async.cg.shared.global [%0], [%1], 16;" :: "r"(s), "l"(g));
}
__device__ __forceinline__ float silu_f(float v) { return v / (1.0f + __expf(-v)); }

__device__ __forceinline__ void mma16816(float* c, const uint32_t* a, const uint32_t* b) {
    asm volatile(
        "mma.sync.aligned.m16n8k16.row.col.f32.f16.f16.f32 "
        "{%0,%1,%2,%3}, {%4,%5,%6,%7}, {%8,%9}, {%0,%1,%2,%3};"
        : "+f"(c[0]), "+f"(c[1]), "+f"(c[2]), "+f"(c[3])
        : "r"(a[0]), "r"(a[1]), "r"(a[2]), "r"(a[3]), "r"(b[0]), "r"(b[1]));
}

// split a pair of fp32 into packed half2 hi + half2 lo (fp16x3 scheme)
__device__ __forceinline__ void splitpair(float x, float y, uint32_t& hi, uint32_t& lo) {
    const __half2 h = __floats2half2_rn(x, y);
    const float2 hf = __half22float2(h);
    const __half2 l = __floats2half2_rn(x - hf.x, y - hf.y);
    hi = *(const uint32_t*)&h;
    lo = *(const uint32_t*)&l;
}

// ================ fp16 grouped GEMM (m16n8k16) ================
// MODE 0: A rows gathered via ptok from g_xh; silu -> half out (perm rows).
// MODE 1: A rows direct (perm order); epilogue scales by pw and atomicAdds
//         into out[token]. Exactly 2 contributions per element -> commutative
//         fp32 add -> bit-deterministic.
#define HSTAGES 4
#define ASTR_H  40                  // halves per A row (32 + 8 pad)
#define A_HALFS (128 * ASTR_H)      // 5120
#define B_HALFS (128 * ASTR_H)      // 5120
#define SFH     (A_HALFS + B_HALFS) // 10240 halves / stage
#define SBYT_H  (SFH * 2)           // 20480 bytes / stage

template <int MODE>
__global__ __launch_bounds__(256, 2)
void hgemm(const __half* __restrict__ A, const __half* __restrict__ Bt,
           __half* __restrict__ Ch, float* __restrict__ Cf,
           int N, int K,
           const int* __restrict__ cnt, const int* __restrict__ off,
           const int* __restrict__ ptok, const float* __restrict__ pw)
{
    extern __shared__ __half smh[];
    const int e = blockIdx.z;
    const int c = cnt[e], o = off[e];
    if ((int)blockIdx.y * 128 >= c) return;
    const int row0 = o + blockIdx.y * 128;
    const int mend = o + c;
    const int n0 = blockIdx.x * 128;
    const __half* Bp = Bt + (long long)e * N * K;

    const int tid = threadIdx.x;
    const uint32_t sbase = cvta_s(smh);

    const __half* aSrc[2]; uint32_t aDst[2];
    const __half* bSrc[2]; uint32_t bDst[2];
#pragma unroll
    for (int i = 0; i < 2; i++) {
        const int idx = tid + i * 256;
        const int ar = idx >> 2, ac = idx & 3;
        int prow = row0 + ar;
        if (prow > mend - 1) prow = mend - 1;
        const long long arow = (MODE == 0) ? (long long)ptok[prow] : (long long)prow;
        aSrc[i] = A + arow * K + ac * 8;
        aDst[i] = sbase + (uint32_t)(ar * 80 + ac * 16);
        const int br = idx >> 2, bc = idx & 3;
        bSrc[i] = Bp + (long long)(n0 + br) * K + bc * 8;
        bDst[i] = sbase + (uint32_t)(A_HALFS * 2 + br * 80 + bc * 16);
    }

    const int nk = K / 32;
#pragma unroll
    for (int s = 0; s < 3; s++) {
#pragma unroll
        for (int i = 0; i < 2; i++) {
            cp16(aDst[i] + s * SBYT_H, aSrc[i] + s * 32);
            cp16(bDst[i] + s * SBYT_H, bSrc[i] + s * 32);
        }
        asm volatile("cp.async.commit_group;" ::: "memory");
    }

    const int wid = tid >> 5, lane = tid & 31;
    const int wm = (wid & 3) * 32, wn = (wid >> 2) * 64;
    const int l4 = lane >> 2, lq = lane & 3;

    float acc[2][8][4];
#pragma unroll
    for (int mt = 0; mt < 2; mt++)
#pragma unroll
        for (int nt = 0; nt < 8; nt++)
#pragma unroll
            for (int q = 0; q < 4; q++) acc[mt][nt][q] = 0.0f;

    for (int kt = 0; kt < nk; kt++) {
        asm volatile("cp.async.wait_group 2;" ::: "memory");
        __syncthreads();
        if (kt + 3 < nk) {
            const int s = (kt + 3) & 3;
#pragma unroll
            for (int i = 0; i < 2; i++) {
                cp16(aDst[i] + s * SBYT_H, aSrc[i] + (kt + 3) * 32);
                cp16(bDst[i] + s * SBYT_H, bSrc[i] + (kt + 3) * 32);
            }
        }
        asm volatile("cp.async.commit_group;" ::: "memory");

        const __half* st = smh + (kt & 3) * SFH;
#pragma unroll
        for (int ks = 0; ks < 2; ks++) {
            const int kk = ks * 16;
            uint32_t a[2][4], b[8][2];
#pragma unroll
            for (int mt = 0; mt < 2; mt++) {
                const __half* ap = st + (wm + mt * 16 + l4) * ASTR_H + kk + 2 * lq;
                a[mt][0] = *(const uint32_t*)(ap);
                a[mt][1] = *(const uint32_t*)(ap + 8 * ASTR_H);
                a[mt][2] = *(const uint32_t*)(ap + 8);
                a[mt][3] = *(const uint32_t*)(ap + 8 * ASTR_H + 8);
            }
#pragma unroll
            for (int nt = 0; nt < 8; nt++) {
                const __half* bp = st + A_HALFS + (wn + nt * 8 + l4) * ASTR_H + kk + 2 * lq;
                b[nt][0] = *(const uint32_t*)(bp);
                b[nt][1] = *(const uint32_t*)(bp + 8);
            }
#pragma unroll
            for (int mt = 0; mt < 2; mt++)
#pragma unroll
                for (int nt = 0; nt < 8; nt++)
                    mma16816(acc[mt][nt], a[mt], b[nt]);
        }
    }

    // epilogue
#pragma unroll
    for (int mt = 0; mt < 2; mt++) {
#pragma unroll
        for (int hr = 0; hr < 2; hr++) {
            const int row = row0 + wm + mt * 16 + l4 + hr * 8;
            if (row < mend) {
                if (MODE == 0) {
                    __half* cp0 = Ch + (long long)row * N + n0 + wn + lq * 2;
#pragma unroll
                    for (int nt = 0; nt < 8; nt++) {
                        const float v0 = silu_f(acc[mt][nt][hr * 2 + 0]);
                        const float v1 = silu_f(acc[mt][nt][hr * 2 + 1]);
                        *(__half2*)(cp0 + nt * 8) = __floats2half2_rn(v0, v1);
                    }
                } else {
                    const int t = ptok[row];
                    const float w = pw[row];
                    float* cp0 = Cf + (long long)t * N + n0 + wn + lq * 2;
#pragma unroll
                    for (int nt = 0; nt < 8; nt++) {
                        atomicAdd(cp0 + nt * 8 + 0, w * acc[mt][nt][hr * 2 + 0]);
                        atomicAdd(cp0 + nt * 8 + 1, w * acc[mt][nt][hr * 2 + 1]);
                    }
                }
            }
        }
    }
}

// ================ router hidden: fp16x3 MMA with K-split ================
#define RSTAGES 3
#define ASTR 36
#define BSTR 136
#define AFL  (128 * ASTR)
#define BFL  (32 * BSTR)
#define SF   (AFL + BFL)
#define SBYT (SF * 4)

__global__ __launch_bounds__(256)
void router_mma(const float* __restrict__ x, const float* __restrict__ rw1,
                float* __restrict__ part)
{
    extern __shared__ float sm[];
    const int kz = blockIdx.x;
    const int row0 = blockIdx.y * 128;
    const int kbase = kz * (DIM / KSPLIT);

    const int tid = threadIdx.x;
    const uint32_t sbase = cvta_s(sm);

    const float* aSrc[4]; uint32_t aDst[4];
    const float* bSrc[4]; uint32_t bDst[4];
#pragma unroll
    for (int i = 0; i < 4; i++) {
        const int cidx = tid + i * 256;
        const int ar = cidx >> 3, ak = (cidx & 7) * 4;
        aSrc[i] = x + (long long)(row0 + ar) * DIM + kbase + ak;
        aDst[i] = sbase + (uint32_t)(ar * ASTR + ak) * 4u;
        const int bk = cidx >> 5, bn = (cidx & 31) * 4;
        bSrc[i] = rw1 + (long long)(kbase + bk) * RH + bn;
        bDst[i] = sbase + (uint32_t)(AFL + bk * BSTR + bn) * 4u;
    }

    const int nk = (DIM / KSPLIT) / 32;    // 8
#pragma unroll
    for (int s = 0; s < 2; s++) {
#pragma unroll
        for (int i = 0; i < 4; i++) {
            cp16(aDst[i] + s * SBYT, aSrc[i] + s * 32);
            cp16(bDst[i] + s * SBYT, bSrc[i] + (long long)s * 32 * RH);
        }
        asm volatile("cp.async.commit_group;" ::: "memory");
    }

    const int wid = tid >> 5, lane = tid & 31;
    const int wm = (wid & 3) * 32, wn = (wid >> 2) * 64;
    const int l4 = lane >> 2, lq = lane & 3;

    float acc[2][8][4];
#pragma unroll
    for (int mt = 0; mt < 2; mt++)
#pragma unroll
        for (int nt = 0; nt < 8; nt++)
#pragma unroll
            for (int q = 0; q < 4; q++) acc[mt][nt][q] = 0.0f;

    int rstage = 0, pstage = 2;
    for (int kt = 0; kt < nk; kt++) {
        asm volatile("cp.async.wait_group 1;" ::: "memory");
        __syncthreads();
        if (kt + 2 < nk) {
#pragma unroll
            for (int i = 0; i < 4; i++) {
                cp16(aDst[i] + pstage * SBYT, aSrc[i] + (kt + 2) * 32);
                cp16(bDst[i] + pstage * SBYT, bSrc[i] + (long long)(kt + 2) * 32 * RH);
            }
        }
        asm volatile("cp.async.commit_group;" ::: "memory");

        const float* st = sm + rstage * SF;
#pragma unroll
        for (int ks = 0; ks < 2; ks++) {
            const int kk = ks * 16;
            uint32_t ah[2][4], al[2][4], bh[8][2], bl[8][2];
#pragma unroll
            for (int mt = 0; mt < 2; mt++) {
                const float* ap = st + (wm + mt * 16 + l4) * ASTR + kk + 2 * lq;
                splitpair(ap[0],              ap[1],              ah[mt][0], al[mt][0]);
                splitpair(ap[8 * ASTR],       ap[8 * ASTR + 1],   ah[mt][1], al[mt][1]);
                splitpair(ap[8],              ap[9],              ah[mt][2], al[mt][2]);
                splitpair(ap[8 * ASTR + 8],   ap[8 * ASTR + 9],   ah[mt][3], al[mt][3]);
            }
#pragma unroll
            for (int nt = 0; nt < 8; nt++) {
                const float* bp = st + AFL + (kk + 2 * lq) * BSTR + wn + nt * 8 + l4;
                splitpair(bp[0],        bp[BSTR],     bh[nt][0], bl[nt][0]);
                splitpair(bp[8 * BSTR], bp[9 * BSTR], bh[nt][1], bl[nt][1]);
            }
#pragma unroll
            for (int mt = 0; mt < 2; mt++)
#pragma unroll
                for (int nt = 0; nt < 8; nt++) {
                    mma16816(acc[mt][nt], ah[mt], bh[nt]);
                    mma16816(acc[mt][nt], ah[mt], bl[nt]);
                    mma16816(acc[mt][nt], al[mt], bh[nt]);
                }
        }
        if (++rstage == RSTAGES) rstage = 0;
        if (++pstage == RSTAGES) pstage = 0;
    }

    float* base = part + (long long)kz * T_TOKENS * RH;
#pragma unroll
    for (int mt = 0; mt < 2; mt++) {
#pragma unroll
        for (int hr = 0; hr < 2; hr++) {
            const int row = row0 + wm + mt * 16 + l4 + hr * 8;
            float* cp0 = base + (long long)row * RH + wn + lq * 2;
#pragma unroll
            for (int nt = 0; nt < 8; nt++) {
                float2 v;
                v.x = acc[mt][nt][hr * 2 + 0];
                v.y = acc[mt][nt][hr * 2 + 1];
                *(float2*)(cp0 + nt * 8) = v;
            }
        }
    }
}

// ---------------- fused: KSPLIT-reduce + silu + logits + top-2 ----------------
__global__ void router_topk_kernel(const float* __restrict__ part,
                                   const float* __restrict__ w2)
{
    const int warp = (blockIdx.x * blockDim.x + threadIdx.x) >> 5;
    const int lane = threadIdx.x & 31;
    if (warp >= T_TOKENS) return;
    const long long stride = (long long)T_TOKENS * RH;
    const long long base = (long long)warp * RH;

    float acc[NEXP];
#pragma unroll
    for (int e = 0; e < NEXP; e++) acc[e] = 0.0f;
#pragma unroll
    for (int j4 = 0; j4 < RH / 32; j4++) {
        const int j = j4 * 32 + lane;
        float s = part[base + j];
#pragma unroll
        for (int kz = 1; kz < KSPLIT; kz++) s += part[base + j + kz * stride];
        s = silu_f(s);
#pragma unroll
        for (int e = 0; e < NEXP; e++) acc[e] += s * w2[j * NEXP + e];
    }
#pragma unroll
    for (int off = 16; off > 0; off >>= 1)
#pragma unroll
        for (int e = 0; e < NEXP; e++)
            acc[e] += __shfl_xor_sync(0xffffffffu, acc[e], off);
    if (lane == 0) {
        float mx = acc[0];
#pragma unroll
        for (int e = 1; e < NEXP; e++) mx = fmaxf(mx, acc[e]);
        float p[NEXP];
#pragma unroll
        for (int e = 0; e < NEXP; e++) p[e] = __expf(acc[e] - mx);
        int i0 = 0;
#pragma unroll
        for (int e = 1; e < NEXP; e++) if (p[e] > p[i0]) i0 = e;
        int i1 = (i0 == 0) ? 1 : 0;
#pragma unroll
        for (int e = 0; e < NEXP; e++) if (e != i0 && p[e] > p[i1]) i1 = e;
        const float s = p[i0] + p[i1];
        const int t = warp;
        int pos0 = atomicAdd(&g_cnt[i0], 1);
        g_tok[i0 * T_TOKENS + pos0]  = t;
        g_slot[i0 * T_TOKENS + pos0] = 2 * t;
        g_rw[2 * t] = p[i0] / s;
        int pos1 = atomicAdd(&g_cnt[i1], 1);
        g_tok[i1 * T_TOKENS + pos1]  = t;
        g_slot[i1 * T_TOKENS + pos1] = 2 * t + 1;
        g_rw[2 * t + 1] = p[i1] / s;
    }
}

// ---------------- conversions ----------------
__global__ void transpose_half_kernel(const float* __restrict__ src,
                                      __half* __restrict__ dst, int R, int C)
{
    __shared__ float tile[32][33];
    const int e = blockIdx.z;
    const float* s = src + (long long)e * R * C;
    __half* d = dst + (long long)e * R * C;
    const int c0 = blockIdx.x * 32, r0 = blockIdx.y * 32;
    const int tx = threadIdx.x, ty = threadIdx.y;
#pragma unroll
    for (int i = 0; i < 32; i += 8)
        tile[ty + i][tx] = s[(long long)(r0 + ty + i) * C + c0 + tx];
    __syncthreads();
#pragma unroll
    for (int i = 0; i < 32; i += 8)
        d[(long long)(c0 + ty + i) * R + r0 + tx] = __float2half_rn(tile[tx][ty + i]);
}

__global__ void x2half_kernel(const float* __restrict__ x, __half* __restrict__ xh)
{
    const int i = blockIdx.x * blockDim.x + threadIdx.x;
    if (i >= T_TOKENS * DIM / 4) return;
    const float4 v = ((const float4*)x)[i];
    const __half2 h0 = __floats2half2_rn(v.x, v.y);
    const __half2 h1 = __floats2half2_rn(v.z, v.w);
    uint2 u;
    u.x = *(const uint32_t*)&h0;
    u.y = *(const uint32_t*)&h1;
    ((uint2*)xh)[i] = u;
}

__global__ void zero_out_kernel(float* __restrict__ out)
{
    const int i = blockIdx.x * blockDim.x + threadIdx.x;
    if (i < T_TOKENS * DIM / 4)
        ((float4*)out)[i] = make_float4(0.f, 0.f, 0.f, 0.f);
}

__global__ void zero_cnt_kernel() { if (threadIdx.x < NEXP) g_cnt[threadIdx.x] = 0; }

__global__ void offsets_kernel() {
    if (threadIdx.x == 0) {
        int s = 0;
        for (int e = 0; e < NEXP; e++) { g_off[e] = s; s += g_cnt[e]; }
    }
}

__global__ void dispatch_meta_kernel()
{
    const int l = blockIdx.x * blockDim.x + threadIdx.x;
    if (l >= NSLOTS) return;
    int e = 0;
#pragma unroll
    for (int k = 1; k < NEXP; k++) if (l >= g_off[k]) e = k;
    const int p = l - g_off[e];
    const int t = g_tok[e * T_TOKENS + p];
    g_ptok[l] = t;
    g_pw[l] = g_rw[g_slot[e * T_TOKENS + p]];
}

// ---------------- host ----------------
extern "C" void kernel_launch(void* const* d_in, const int* in_sizes, int n_in,
                              void* d_out, int out_size)
{
    const float* x   = (const float*)d_in[0];
    const float* rw1 = (const float*)d_in[1];
    const float* rw2 = (const float*)d_in[2];
    const float* W1  = (const float*)d_in[3];
    const float* W2  = (const float*)d_in[4];
    float* out = (float*)d_out;

    void *xh, *hp, *w1t, *w2t, *rpart, *cntp, *offp, *ptokp, *pwp;
    cudaGetSymbolAddress(&xh, g_xh);
    cudaGetSymbolAddress(&hp, g_h);
    cudaGetSymbolAddress(&w1t, g_w1t);
    cudaGetSymbolAddress(&w2t, g_w2t);
    cudaGetSymbolAddress(&rpart, g_rpart);
    cudaGetSymbolAddress(&cntp, g_cnt);
    cudaGetSymbolAddress(&offp, g_off);
    cudaGetSymbolAddress(&ptokp, g_ptok);
    cudaGetSymbolAddress(&pwp, g_pw);

    const int SMEM_H = HSTAGES * SBYT_H;   // 81920
    const int SMEM_R = RSTAGES * SBYT;     // 107520
    cudaFuncSetAttribute(hgemm<0>,
                         cudaFuncAttributeMaxDynamicSharedMemorySize, SMEM_H);
    cudaFuncSetAttribute(hgemm<1>,
                         cudaFuncAttributeMaxDynamicSharedMemorySize, SMEM_H);
    cudaFuncSetAttribute(router_mma,
                         cudaFuncAttributeMaxDynamicSharedMemorySize, SMEM_R);

    // side stream with dependency-matched split joins
    cudaStream_t s1;
    cudaStreamCreate(&s1);
    cudaEvent_t e0, e1, e2;
    cudaEventCreateWithFlags(&e0, cudaEventDisableTiming);
    cudaEventCreateWithFlags(&e1, cudaEventDisableTiming);
    cudaEventCreateWithFlags(&e2, cudaEventDisableTiming);

    // 1. zero counters (main); fork side stream
    zero_cnt_kernel<<<1, 32>>>();
    cudaEventRecord(e0, 0);
    cudaStreamWaitEvent(s1, e0, 0);

    // 2a. side stream, phase 1: GEMM1 prerequisites only (W1^T + x->half)
    transpose_half_kernel<<<dim3(FF / 32, DIM / 32, NEXP), dim3(32, 8), 0, s1>>>(
        W1, (__half*)w1t, DIM, FF);
    x2half_kernel<<<(T_TOKENS * DIM / 4 + 255) / 256, 256, 0, s1>>>(x, (__half*)xh);
    cudaEventRecord(e1, s1);

    // 2b. side stream, phase 2: GEMM2 prerequisites (W2^T + out-zero);
    //     hides under hgemm1 (~240us).
    transpose_half_kernel<<<dim3(DIM / 32, FF / 32, NEXP), dim3(32, 8), 0, s1>>>(
        W2, (__half*)w2t, FF, DIM);
    zero_out_kernel<<<(T_TOKENS * DIM / 4 + 255) / 256, 256, 0, s1>>>(out);
    cudaEventRecord(e2, s1);

    // 3. router hidden partials (fp16x3 K-split MMA) — concurrent with side
    router_mma<<<dim3(KSPLIT, T_TOKENS / 128), 256, SMEM_R>>>(x, rw1, (float*)rpart);

    // 4. fused reduce+silu+logits+top-2
    router_topk_kernel<<<T_TOKENS / 8, 256>>>((const float*)rpart, rw2);

    // 5. offsets + perm-row metadata
    offsets_kernel<<<1, 32>>>();
    dispatch_meta_kernel<<<(NSLOTS + 255) / 256, 256>>>();

    // join 1: only GEMM1's prerequisites
    cudaStreamWaitEvent(0, e1, 0);

    // 6. grouped GEMM1 (gather-A): h = silu(x[tok] @ W1[e])
    hgemm<0><<<dim3(FF / 128, T_TOKENS / 128, NEXP), 256, SMEM_H>>>(
        (const __half*)xh, (const __half*)w1t, (__half*)hp, (float*)0,
        FF, DIM, (const int*)cntp, (const int*)offp,
        (const int*)ptokp, (const float*)pwp);

    // join 2: GEMM2's prerequisites (already done by now)
    cudaStreamWaitEvent(0, e2, 0);

    // 7. grouped GEMM2 (weighted atomic scatter): out[t] += w * (h @ W2[e])
    hgemm<1><<<dim3(DIM / 128, T_TOKENS / 128, NEXP), 256, SMEM_H>>>(
        (const __half*)hp, (const __half*)w2t, (__half*)0, out,
        DIM, FF, (const int*)cntp, (const int*)offp,
        (const int*)ptokp, (const float*)pwp);
}